// round 3
// baseline (speedup 1.0000x reference)
#include <cuda_runtime.h>
#include <cuda_fp16.h>
#include <cstdint>

#define DEV __device__ __forceinline__

static constexpr int B_  = 8;
static constexpr int T_  = 4096;
static constexpr int D_  = 1024;
static constexpr int BT  = B_ * T_;        // 32768
static constexpr int N2  = 2 * D_;         // 2048
static constexpr int NCH = 64;
static constexpr int CL  = T_ / NCH;       // 64
static constexpr float LN_EPS = 1e-6f;

__device__ __align__(16) __half g_xh[(size_t)BT * D_];   // x in fp16
__device__ __align__(16) __half g_wt[(size_t)N2 * D_];   // W^T fp16 [2048,1024]
__device__ __align__(16) float  g_c [(size_t)BT * D_];   // gate coeff
__device__ __align__(16) float  g_v [(size_t)BT * D_];   // gate value
__device__ float g_A [B_ * NCH * D_];
__device__ float g_Hl[B_ * NCH * D_];
__device__ float g_Hp[B_ * NCH * D_];

DEV uint32_t smem_u32(const void* p) {
    uint32_t a;
    asm("{ .reg .u64 t; cvta.to.shared.u64 t, %1; cvt.u32.u64 %0, t; }" : "=r"(a) : "l"(p));
    return a;
}

#define CP16(dst, src) \
    asm volatile("cp.async.cg.shared.global [%0], [%1], 16;" :: "r"(dst), "l"(src) : "memory")
#define CP_COMMIT() asm volatile("cp.async.commit_group;" ::: "memory")
#define CP_WAIT(N)  asm volatile("cp.async.wait_group %0;" :: "n"(N) : "memory")

#define LDSM4(r0, r1, r2, r3, addr) \
    asm volatile("ldmatrix.sync.aligned.m8n8.x4.shared.b16 {%0,%1,%2,%3}, [%4];" \
        : "=r"(r0), "=r"(r1), "=r"(r2), "=r"(r3) : "r"(addr))

#define MMA(d, a0, a1, a2, a3, b0, b1) \
    asm volatile("mma.sync.aligned.m16n8k16.row.col.f32.f16.f16.f32 " \
        "{%0,%1,%2,%3}, {%4,%5,%6,%7}, {%8,%9}, {%0,%1,%2,%3};" \
        : "+f"((d)[0]), "+f"((d)[1]), "+f"((d)[2]), "+f"((d)[3]) \
        : "r"(a0), "r"(a1), "r"(a2), "r"(a3), "r"(b0), "r"(b1))

// ---------------- K0a: x fp32 -> fp16 ----------------
__global__ void k_cvt_x(const float4* __restrict__ x4) {
    size_t i = (size_t)blockIdx.x * blockDim.x + threadIdx.x;
    if (i < (size_t)BT * D_ / 4) {
        float4 v = x4[i];
        __half2 h0 = __floats2half2_rn(v.x, v.y);
        __half2 h1 = __floats2half2_rn(v.z, v.w);
        uint2 u;
        u.x = *reinterpret_cast<uint32_t*>(&h0);
        u.y = *reinterpret_cast<uint32_t*>(&h1);
        reinterpret_cast<uint2*>(g_xh)[i] = u;
    }
}

// ---------------- K0b: W[D,2D] -> W^T fp16 [2D,D] ----------------
__global__ void k_wt(const float* __restrict__ W) {
    __shared__ float tile[32][33];
    int e0 = blockIdx.x * 32, d0 = blockIdx.y * 32;
    int tx = threadIdx.x, ty = threadIdx.y;
#pragma unroll
    for (int j = 0; j < 4; ++j)
        tile[ty + 8 * j][tx] = W[(size_t)(d0 + ty + 8 * j) * N2 + e0 + tx];
    __syncthreads();
#pragma unroll
    for (int j = 0; j < 4; ++j)
        g_wt[(size_t)(e0 + ty + 8 * j) * D_ + d0 + tx] = __float2half_rn(tile[tx][ty + 8 * j]);
}

// ---------------- K1: HMMA GEMM + gate epilogue ----------------
static constexpr int ROWB   = 80;              // smem bytes per 32-half row (padded)
static constexpr int TILE_B = 128 * ROWB;      // 10240 B per operand tile
static constexpr int NBUF   = 4;
static constexpr int SMEM_PIPE = NBUF * 2 * TILE_B;    // 81920
static constexpr int SMEM_EPI  = 2 * 128 * 72 * 4;     // 73728
static constexpr int SMEM_DYN  = (SMEM_PIPE > SMEM_EPI) ? SMEM_PIPE : SMEM_EPI;

DEV void gate(float ht, float kk, float& c, float& v) {
    float ek = __expf(kk);
    c = 1.f / (1.f + ek);                   // sigmoid(-k) = exp(log_coeffs)
    float z = 1.f - c;                      // sigmoid(k)
    float g = (ht >= 0.f) ? (ht + 0.5f) : (1.f / (1.f + __expf(-ht)));
    v = z * g;
}

DEV void load_tile(uint32_t sb, int kt, int buf, int m0, int j0, int tid) {
    uint32_t Ab = sb + (uint32_t)buf * (2 * TILE_B);
    uint32_t Bb = Ab + TILE_B;
#pragma unroll
    for (int i = 0; i < 2; ++i) {
        int ch = tid + 256 * i;
        int r = ch >> 2, cth = ch & 3;
        const __half* s = g_xh + (size_t)(m0 + r) * D_ + kt * 32 + cth * 8;
        CP16(Ab + (uint32_t)r * ROWB + cth * 16, s);
    }
#pragma unroll
    for (int i = 0; i < 2; ++i) {
        int ch = tid + 256 * i;
        int r = ch >> 2, cth = ch & 3;
        int e = (r < 64) ? (j0 + r) : (1024 + j0 + r - 64);
        const __half* s = g_wt + (size_t)e * D_ + kt * 32 + cth * 8;
        CP16(Bb + (uint32_t)r * ROWB + cth * 16, s);
    }
}

__global__ void __launch_bounds__(256) k_gemm(const float* __restrict__ bias) {
    extern __shared__ char smem[];
    uint32_t sb = smem_u32(smem);
    int tid = threadIdx.x;
    int wid = tid >> 5, lane = tid & 31;
    int m0 = blockIdx.y * 128;
    int j0 = blockIdx.x * 64;

    float acc1[8][4] = {};   // h~ tile accumulators
    float acc2[8][4] = {};   // k  tile accumulators

    load_tile(sb, 0, 0, m0, j0, tid); CP_COMMIT();
    load_tile(sb, 1, 1, m0, j0, tid); CP_COMMIT();

    uint32_t aoff = (uint32_t)(wid * 16 + (lane & 15)) * ROWB + (uint32_t)((lane >> 4) << 4);
    uint32_t boff = (uint32_t)(((lane & 7) | ((lane >> 4) << 3))) * ROWB
                  + (uint32_t)(((lane >> 3) & 1) << 4);

#pragma unroll 1
    for (int kt = 0; kt < 32; ++kt) {
        if (kt + 2 < 32) { load_tile(sb, kt + 2, (kt + 2) & 3, m0, j0, tid); CP_COMMIT(); }
        if (kt < 30)      CP_WAIT(2);
        else if (kt == 30) CP_WAIT(1);
        else               CP_WAIT(0);
        __syncthreads();

        uint32_t Ab = sb + (uint32_t)(kt & 3) * (2 * TILE_B);
        uint32_t Bb = Ab + TILE_B;
#pragma unroll
        for (int s = 0; s < 2; ++s) {
            uint32_t a0, a1, a2, a3;
            LDSM4(a0, a1, a2, a3, Ab + aoff + s * 32);
#pragma unroll
            for (int g4 = 0; g4 < 4; ++g4) {
                uint32_t b0, b1, b2, b3;
                LDSM4(b0, b1, b2, b3, Bb + (uint32_t)(g4 * 16) * ROWB + boff + s * 32);
                MMA(acc1[2 * g4],     a0, a1, a2, a3, b0, b1);
                MMA(acc1[2 * g4 + 1], a0, a1, a2, a3, b2, b3);
            }
#pragma unroll
            for (int g4 = 0; g4 < 4; ++g4) {
                uint32_t b0, b1, b2, b3;
                LDSM4(b0, b1, b2, b3, Bb + (uint32_t)(64 + g4 * 16) * ROWB + boff + s * 32);
                MMA(acc2[2 * g4],     a0, a1, a2, a3, b0, b1);
                MMA(acc2[2 * g4 + 1], a0, a1, a2, a3, b2, b3);
            }
        }
    }
    __syncthreads();   // pipeline drained; safe to reuse smem

    // ---- gate epilogue through smem staging (stride 72 floats) ----
    float* cst = (float*)smem;
    float* vst = cst + 128 * 72;
    int r0 = wid * 16 + (lane >> 2);
    int c0 = (lane & 3) * 2;
#pragma unroll
    for (int nt = 0; nt < 8; ++nt) {
        int ct = nt * 8 + c0;
        float b1a = bias[j0 + ct],        b1b = bias[j0 + ct + 1];
        float b2a = bias[1024 + j0 + ct], b2b = bias[1024 + j0 + ct + 1];
        float c, v;
        gate(acc1[nt][0] + b1a, acc2[nt][0] + b2a, c, v);
        cst[r0 * 72 + ct] = c;            vst[r0 * 72 + ct] = v;
        gate(acc1[nt][1] + b1b, acc2[nt][1] + b2b, c, v);
        cst[r0 * 72 + ct + 1] = c;        vst[r0 * 72 + ct + 1] = v;
        gate(acc1[nt][2] + b1a, acc2[nt][2] + b2a, c, v);
        cst[(r0 + 8) * 72 + ct] = c;      vst[(r0 + 8) * 72 + ct] = v;
        gate(acc1[nt][3] + b1b, acc2[nt][3] + b2b, c, v);
        cst[(r0 + 8) * 72 + ct + 1] = c;  vst[(r0 + 8) * 72 + ct + 1] = v;
    }
    __syncthreads();
#pragma unroll
    for (int i = 0; i < 8; ++i) {
        int e = i * 256 + tid;
        int r = e >> 4, q = e & 15;
        size_t go = (size_t)(m0 + r) * D_ + j0 + q * 4;
        *(float4*)(g_c + go) = *(float4*)(cst + r * 72 + q * 4);
        *(float4*)(g_v + go) = *(float4*)(vst + r * 72 + q * 4);
    }
}

// ---------------- K2: per-chunk local aggregates ----------------
__global__ void __launch_bounds__(1024) k_scan1() {
    int bc = blockIdx.x;
    int d  = threadIdx.x;
    size_t base = (size_t)bc * CL * D_ + d;
    float a = 1.f, h = 0.f;
#pragma unroll 4
    for (int t = 0; t < CL; ++t) {
        float c = g_c[base + (size_t)t * D_];
        float v = g_v[base + (size_t)t * D_];
        h = fmaf(c, h, v);
        a *= c;
    }
    g_A [bc * D_ + d] = a;
    g_Hl[bc * D_ + d] = h;
}

// ---------------- K3: sequential cross-chunk prefix ----------------
__global__ void k_scan2() {
    int t = blockIdx.x * blockDim.x + threadIdx.x;
    if (t >= B_ * D_) return;
    int b = t >> 10, d = t & (D_ - 1);
    float H = 0.f;
#pragma unroll 1
    for (int ch = 0; ch < NCH; ++ch) {
        int idx = (b * NCH + ch) * D_ + d;
        g_Hp[idx] = H;
        H = g_Hl[idx] + g_A[idx] * H;
    }
}

// ---------------- K4: replay + residual + fused LayerNorm ----------------
__global__ void __launch_bounds__(1024) k_scan3(const float* __restrict__ x,
        const float* __restrict__ gamma, const float* __restrict__ beta,
        float* __restrict__ out) {
    __shared__ float red[32];
    __shared__ float s_mu, s_rs;
    int bc = blockIdx.x;
    int d = threadIdx.x;
    int lane = d & 31, wrp = d >> 5;
    float h = g_Hp[bc * D_ + d];
    float ga = gamma[d], be = beta[d];
    size_t base = (size_t)bc * CL * D_ + d;
#pragma unroll 1
    for (int t = 0; t < CL; ++t) {
        size_t idx = base + (size_t)t * D_;
        h = fmaf(g_c[idx], h, g_v[idx]);
        float y = x[idx] + h;
        float s = y;
#pragma unroll
        for (int o = 16; o; o >>= 1) s += __shfl_xor_sync(~0u, s, o);
        if (lane == 0) red[wrp] = s;
        __syncthreads();
        if (wrp == 0) {
            float v = red[lane];
#pragma unroll
            for (int o = 16; o; o >>= 1) v += __shfl_xor_sync(~0u, v, o);
            if (lane == 0) s_mu = v * (1.f / 1024.f);
        }
        __syncthreads();
        float dy = y - s_mu;
        float q = dy * dy;
#pragma unroll
        for (int o = 16; o; o >>= 1) q += __shfl_xor_sync(~0u, q, o);
        if (lane == 0) red[wrp] = q;
        __syncthreads();
        if (wrp == 0) {
            float v = red[lane];
#pragma unroll
            for (int o = 16; o; o >>= 1) v += __shfl_xor_sync(~0u, v, o);
            if (lane == 0) s_rs = rsqrtf(v * (1.f / 1024.f) + LN_EPS);
        }
        __syncthreads();
        out[idx] = dy * s_rs * ga + be;
    }
}

extern "C" void kernel_launch(void* const* d_in, const int* in_sizes, int n_in,
                              void* d_out, int out_size) {
    const float* x     = (const float*)d_in[0];
    const float* W     = (const float*)d_in[1];
    const float* b     = (const float*)d_in[2];
    const float* gamma = (const float*)d_in[3];
    const float* beta  = (const float*)d_in[4];
    float* out = (float*)d_out;

    cudaFuncSetAttribute(k_gemm, cudaFuncAttributeMaxDynamicSharedMemorySize, SMEM_DYN);

    k_cvt_x<<<(BT * (D_ / 4) + 255) / 256, 256>>>((const float4*)x);
    k_wt<<<dim3(N2 / 32, D_ / 32), dim3(32, 8)>>>(W);
    k_gemm<<<dim3(D_ / 64, BT / 128), 256, SMEM_DYN>>>(b);
    k_scan1<<<B_ * NCH, 1024>>>();
    k_scan2<<<(B_ * D_ + 255) / 256, 256>>>();
    k_scan3<<<B_ * NCH, 1024>>>(x, gamma, beta, out);
}

// round 4
// speedup vs baseline: 1.2114x; 1.2114x over previous
#include <cuda_runtime.h>
#include <cuda_fp16.h>
#include <cstdint>

#define DEV __device__ __forceinline__

static constexpr int B_  = 8;
static constexpr int T_  = 4096;
static constexpr int D_  = 1024;
static constexpr int BT  = B_ * T_;        // 32768
static constexpr int N2  = 2 * D_;         // 2048
static constexpr int NCH = 64;
static constexpr int CL  = T_ / NCH;       // 64
static constexpr float LN_EPS = 1e-6f;

__device__ __align__(16) __half g_xh[(size_t)BT * D_];   // x in fp16
__device__ __align__(16) __half g_wt[(size_t)N2 * D_];   // W^T fp16 [2048,1024]
__device__ __align__(16) __half g_ch[(size_t)BT * D_];   // gate coeff (fp16)
__device__ __align__(16) __half g_vh[(size_t)BT * D_];   // gate value (fp16)
__device__ float g_A [B_ * NCH * D_];
__device__ float g_Hl[B_ * NCH * D_];
__device__ float g_Hp[B_ * NCH * D_];

DEV uint32_t smem_u32(const void* p) {
    uint32_t a;
    asm("{ .reg .u64 t; cvta.to.shared.u64 t, %1; cvt.u32.u64 %0, t; }" : "=r"(a) : "l"(p));
    return a;
}

#define CP16(dst, src) \
    asm volatile("cp.async.cg.shared.global [%0], [%1], 16;" :: "r"(dst), "l"(src) : "memory")
#define CP_COMMIT() asm volatile("cp.async.commit_group;" ::: "memory")
#define CP_WAIT(N)  asm volatile("cp.async.wait_group %0;" :: "n"(N) : "memory")

#define LDSM4(r0, r1, r2, r3, addr) \
    asm volatile("ldmatrix.sync.aligned.m8n8.x4.shared.b16 {%0,%1,%2,%3}, [%4];" \
        : "=r"(r0), "=r"(r1), "=r"(r2), "=r"(r3) : "r"(addr))

#define MMA(d, a0, a1, a2, a3, b0, b1) \
    asm volatile("mma.sync.aligned.m16n8k16.row.col.f32.f16.f16.f32 " \
        "{%0,%1,%2,%3}, {%4,%5,%6,%7}, {%8,%9}, {%0,%1,%2,%3};" \
        : "+f"((d)[0]), "+f"((d)[1]), "+f"((d)[2]), "+f"((d)[3]) \
        : "r"(a0), "r"(a1), "r"(a2), "r"(a3), "r"(b0), "r"(b1))

// ---------------- K0a: x fp32 -> fp16 ----------------
__global__ void k_cvt_x(const float4* __restrict__ x4) {
    size_t i = (size_t)blockIdx.x * blockDim.x + threadIdx.x;
    if (i < (size_t)BT * D_ / 4) {
        float4 v = x4[i];
        __half2 h0 = __floats2half2_rn(v.x, v.y);
        __half2 h1 = __floats2half2_rn(v.z, v.w);
        uint2 u;
        u.x = *reinterpret_cast<uint32_t*>(&h0);
        u.y = *reinterpret_cast<uint32_t*>(&h1);
        reinterpret_cast<uint2*>(g_xh)[i] = u;
    }
}

// ---------------- K0b: W[D,2D] -> W^T fp16 [2D,D] ----------------
__global__ void k_wt(const float* __restrict__ W) {
    __shared__ float tile[32][33];
    int e0 = blockIdx.x * 32, d0 = blockIdx.y * 32;
    int tx = threadIdx.x, ty = threadIdx.y;
#pragma unroll
    for (int j = 0; j < 4; ++j)
        tile[ty + 8 * j][tx] = W[(size_t)(d0 + ty + 8 * j) * N2 + e0 + tx];
    __syncthreads();
#pragma unroll
    for (int j = 0; j < 4; ++j)
        g_wt[(size_t)(e0 + ty + 8 * j) * D_ + d0 + tx] = __float2half_rn(tile[tx][ty + 8 * j]);
}

// ---------------- K1: HMMA GEMM + gate epilogue + fused local scan ----------------
static constexpr int ROWB   = 80;              // smem bytes per 32-half row (padded)
static constexpr int TILE_B = 128 * ROWB;      // 10240 B per operand tile
static constexpr int NBUF   = 4;
static constexpr int SMEM_PIPE = NBUF * 2 * TILE_B;        // 81920
static constexpr int SMEM_EPI  = 2 * 128 * 72 * 4 + 2048;  // staging + seg aggregates
static constexpr int SMEM_DYN  = (SMEM_PIPE > SMEM_EPI) ? SMEM_PIPE : SMEM_EPI;

DEV void gate(float ht, float kk, float& c, float& v) {
    float ek = __expf(kk);
    c = 1.f / (1.f + ek);                   // sigmoid(-k) = exp(log_coeffs)
    float z = 1.f - c;                      // sigmoid(k)
    float g = (ht >= 0.f) ? (ht + 0.5f) : (1.f / (1.f + __expf(-ht)));
    v = z * g;
}

DEV void load_tile(uint32_t sb, int kt, int buf, int m0, int j0, int tid) {
    uint32_t Ab = sb + (uint32_t)buf * (2 * TILE_B);
    uint32_t Bb = Ab + TILE_B;
#pragma unroll
    for (int i = 0; i < 2; ++i) {
        int ch = tid + 256 * i;
        int r = ch >> 2, cth = ch & 3;
        const __half* s = g_xh + (size_t)(m0 + r) * D_ + kt * 32 + cth * 8;
        CP16(Ab + (uint32_t)r * ROWB + cth * 16, s);
    }
#pragma unroll
    for (int i = 0; i < 2; ++i) {
        int ch = tid + 256 * i;
        int r = ch >> 2, cth = ch & 3;
        int e = (r < 64) ? (j0 + r) : (1024 + j0 + r - 64);
        const __half* s = g_wt + (size_t)e * D_ + kt * 32 + cth * 8;
        CP16(Bb + (uint32_t)r * ROWB + cth * 16, s);
    }
}

__global__ void __launch_bounds__(256) k_gemm(const float* __restrict__ bias) {
    extern __shared__ char smem[];
    uint32_t sb = smem_u32(smem);
    int tid = threadIdx.x;
    int wid = tid >> 5, lane = tid & 31;
    int m0 = blockIdx.y * 128;
    int j0 = blockIdx.x * 64;

    float acc1[8][4] = {};   // h~ tile accumulators
    float acc2[8][4] = {};   // k  tile accumulators

    load_tile(sb, 0, 0, m0, j0, tid); CP_COMMIT();
    load_tile(sb, 1, 1, m0, j0, tid); CP_COMMIT();

    uint32_t aoff = (uint32_t)(wid * 16 + (lane & 15)) * ROWB + (uint32_t)((lane >> 4) << 4);
    uint32_t boff = (uint32_t)(((lane & 7) | ((lane >> 4) << 3))) * ROWB
                  + (uint32_t)(((lane >> 3) & 1) << 4);

#pragma unroll 1
    for (int kt = 0; kt < 32; ++kt) {
        if (kt + 2 < 32) { load_tile(sb, kt + 2, (kt + 2) & 3, m0, j0, tid); CP_COMMIT(); }
        if (kt < 30)      CP_WAIT(2);
        else if (kt == 30) CP_WAIT(1);
        else               CP_WAIT(0);
        __syncthreads();

        uint32_t Ab = sb + (uint32_t)(kt & 3) * (2 * TILE_B);
        uint32_t Bb = Ab + TILE_B;
#pragma unroll
        for (int s = 0; s < 2; ++s) {
            uint32_t a0, a1, a2, a3;
            LDSM4(a0, a1, a2, a3, Ab + aoff + s * 32);
#pragma unroll
            for (int g4 = 0; g4 < 4; ++g4) {
                uint32_t b0, b1, b2, b3;
                LDSM4(b0, b1, b2, b3, Bb + (uint32_t)(g4 * 16) * ROWB + boff + s * 32);
                MMA(acc1[2 * g4],     a0, a1, a2, a3, b0, b1);
                MMA(acc1[2 * g4 + 1], a0, a1, a2, a3, b2, b3);
            }
#pragma unroll
            for (int g4 = 0; g4 < 4; ++g4) {
                uint32_t b0, b1, b2, b3;
                LDSM4(b0, b1, b2, b3, Bb + (uint32_t)(64 + g4 * 16) * ROWB + boff + s * 32);
                MMA(acc2[2 * g4],     a0, a1, a2, a3, b0, b1);
                MMA(acc2[2 * g4 + 1], a0, a1, a2, a3, b2, b3);
            }
        }
    }
    __syncthreads();   // pipeline drained; safe to reuse smem

    // ---- gate epilogue through smem staging (stride 72 floats) ----
    float* cst = (float*)smem;
    float* vst = cst + 128 * 72;
    float* sA  = vst + 128 * 72;     // 256 seg aggregates
    float* sH  = sA + 256;
    int r0 = wid * 16 + (lane >> 2);
    int c0 = (lane & 3) * 2;
#pragma unroll
    for (int nt = 0; nt < 8; ++nt) {
        int ct = nt * 8 + c0;
        float b1a = bias[j0 + ct],        b1b = bias[j0 + ct + 1];
        float b2a = bias[1024 + j0 + ct], b2b = bias[1024 + j0 + ct + 1];
        float c, v;
        gate(acc1[nt][0] + b1a, acc2[nt][0] + b2a, c, v);
        cst[r0 * 72 + ct] = c;            vst[r0 * 72 + ct] = v;
        gate(acc1[nt][1] + b1b, acc2[nt][1] + b2b, c, v);
        cst[r0 * 72 + ct + 1] = c;        vst[r0 * 72 + ct + 1] = v;
        gate(acc1[nt][2] + b1a, acc2[nt][2] + b2a, c, v);
        cst[(r0 + 8) * 72 + ct] = c;      vst[(r0 + 8) * 72 + ct] = v;
        gate(acc1[nt][3] + b1b, acc2[nt][3] + b2b, c, v);
        cst[(r0 + 8) * 72 + ct + 1] = c;  vst[(r0 + 8) * 72 + ct + 1] = v;
    }
    __syncthreads();

    // fused local scan, phase 1: each thread scans 32 rows of one d-column
    {
        int seg  = tid >> 6;            // (chunk<<1)|half
        int dcol = tid & 63;
        int rs = seg * 32;
        float a = 1.f, h = 0.f;
#pragma unroll 8
        for (int t = 0; t < 32; ++t) {
            float c = cst[(rs + t) * 72 + dcol];
            float v = vst[(rs + t) * 72 + dcol];
            h = fmaf(c, h, v);
            a *= c;
        }
        sA[tid] = a; sH[tid] = h;
    }

    // coalesced fp16 stores of c/v (no sync needed: reads only cst/vst)
#pragma unroll
    for (int i = 0; i < 8; ++i) {
        int e = i * 256 + tid;
        int r = e >> 4, q = e & 15;
        size_t go = (size_t)(m0 + r) * D_ + j0 + q * 4;
        float4 cf = *(float4*)(cst + r * 72 + q * 4);
        float4 vf = *(float4*)(vst + r * 72 + q * 4);
        __half2 ca = __floats2half2_rn(cf.x, cf.y), cb = __floats2half2_rn(cf.z, cf.w);
        __half2 va = __floats2half2_rn(vf.x, vf.y), vb = __floats2half2_rn(vf.z, vf.w);
        uint2 cu, vu;
        cu.x = *(uint32_t*)&ca; cu.y = *(uint32_t*)&cb;
        vu.x = *(uint32_t*)&va; vu.y = *(uint32_t*)&vb;
        *(uint2*)(g_ch + go) = cu;
        *(uint2*)(g_vh + go) = vu;
    }
    __syncthreads();

    // fused local scan, phase 2: combine halves -> chunk aggregates
    if (tid < 128) {
        int chunk = tid >> 6, dcol = tid & 63;
        float aLo = sA[chunk * 128 + dcol],      hLo = sH[chunk * 128 + dcol];
        float aHi = sA[chunk * 128 + 64 + dcol], hHi = sH[chunk * 128 + 64 + dcol];
        int bc = (m0 >> 6) + chunk;
        g_A [bc * D_ + j0 + dcol] = aLo * aHi;
        g_Hl[bc * D_ + j0 + dcol] = fmaf(aHi, hLo, hHi);
    }
}

// ---------------- K3: sequential cross-chunk prefix ----------------
__global__ void k_scan2() {
    int t = blockIdx.x * blockDim.x + threadIdx.x;
    if (t >= B_ * D_) return;
    int b = t >> 10, d = t & (D_ - 1);
    float H = 0.f;
#pragma unroll 4
    for (int ch = 0; ch < NCH; ++ch) {
        int idx = (b * NCH + ch) * D_ + d;
        g_Hp[idx] = H;
        H = g_Hl[idx] + g_A[idx] * H;
    }
}

// ---------------- K4: replay + residual + fused LayerNorm ----------------
__global__ void __launch_bounds__(512) k_scan3(const float* __restrict__ x,
        const float* __restrict__ gamma, const float* __restrict__ beta,
        float* __restrict__ out) {
    __shared__ float red[16];
    __shared__ float s_mu, s_rs;
    int bc = blockIdx.x;
    int tid = threadIdx.x;
    int lane = tid & 31, wrp = tid >> 5;
    int d2 = tid * 2;
    float h0 = g_Hp[bc * D_ + d2];
    float h1 = g_Hp[bc * D_ + d2 + 1];
    float2 ga = *(const float2*)(gamma + d2);
    float2 be = *(const float2*)(beta + d2);
    size_t base = (size_t)bc * CL * D_ + d2;
#pragma unroll 1
    for (int t = 0; t < CL; ++t) {
        size_t idx = base + (size_t)t * D_;
        __half2 c2 = *(const __half2*)(g_ch + idx);
        __half2 v2 = *(const __half2*)(g_vh + idx);
        float2 cf = __half22float2(c2);
        float2 vf = __half22float2(v2);
        h0 = fmaf(cf.x, h0, vf.x);
        h1 = fmaf(cf.y, h1, vf.y);
        float2 xx = *(const float2*)(x + idx);
        float y0 = xx.x + h0, y1 = xx.y + h1;
        float s = y0 + y1;
#pragma unroll
        for (int o = 16; o; o >>= 1) s += __shfl_xor_sync(~0u, s, o);
        if (lane == 0) red[wrp] = s;
        __syncthreads();
        if (wrp == 0) {
            float v = (lane < 16) ? red[lane] : 0.f;
#pragma unroll
            for (int o = 8; o; o >>= 1) v += __shfl_xor_sync(~0u, v, o);
            if (lane == 0) s_mu = v * (1.f / 1024.f);
        }
        __syncthreads();
        float mu = s_mu;
        float dy0 = y0 - mu, dy1 = y1 - mu;
        float q = dy0 * dy0 + dy1 * dy1;
#pragma unroll
        for (int o = 16; o; o >>= 1) q += __shfl_xor_sync(~0u, q, o);
        if (lane == 0) red[wrp] = q;
        __syncthreads();
        if (wrp == 0) {
            float v = (lane < 16) ? red[lane] : 0.f;
#pragma unroll
            for (int o = 8; o; o >>= 1) v += __shfl_xor_sync(~0u, v, o);
            if (lane == 0) s_rs = rsqrtf(v * (1.f / 1024.f) + LN_EPS);
        }
        __syncthreads();
        float rs = s_rs;
        float2 o2;
        o2.x = dy0 * rs * ga.x + be.x;
        o2.y = dy1 * rs * ga.y + be.y;
        *(float2*)(out + idx) = o2;
    }
}

extern "C" void kernel_launch(void* const* d_in, const int* in_sizes, int n_in,
                              void* d_out, int out_size) {
    const float* x     = (const float*)d_in[0];
    const float* W     = (const float*)d_in[1];
    const float* b     = (const float*)d_in[2];
    const float* gamma = (const float*)d_in[3];
    const float* beta  = (const float*)d_in[4];
    float* out = (float*)d_out;

    cudaFuncSetAttribute(k_gemm, cudaFuncAttributeMaxDynamicSharedMemorySize, SMEM_DYN);

    k_cvt_x<<<(BT * (D_ / 4) + 255) / 256, 256>>>((const float4*)x);
    k_wt<<<dim3(N2 / 32, D_ / 32), dim3(32, 8)>>>(W);
    k_gemm<<<dim3(D_ / 64, BT / 128), 256, SMEM_DYN>>>(b);
    k_scan2<<<(B_ * D_ + 255) / 256, 256>>>();
    k_scan3<<<B_ * NCH, 512>>>(x, gamma, beta, out);
}

// round 5
// speedup vs baseline: 1.3299x; 1.0979x over previous
#include <cuda_runtime.h>
#include <cuda_fp16.h>
#include <cstdint>

#define DEV __device__ __forceinline__

static constexpr int B_  = 8;
static constexpr int T_  = 4096;
static constexpr int D_  = 1024;
static constexpr int BT  = B_ * T_;        // 32768
static constexpr int N2  = 2 * D_;         // 2048
static constexpr int NCH = 64;
static constexpr int CL  = T_ / NCH;       // 64
static constexpr float LN_EPS = 1e-6f;

__device__ __align__(16) __half g_xh[(size_t)BT * D_];   // x in fp16
__device__ __align__(16) __half g_wt[(size_t)N2 * D_];   // W^T fp16 [2048,1024]
__device__ __align__(16) __half g_ch[(size_t)BT * D_];   // gate coeff (fp16)
__device__ __align__(16) __half g_vh[(size_t)BT * D_];   // gate value (fp16)
__device__ float g_A [B_ * NCH * D_];
__device__ float g_Hl[B_ * NCH * D_];
__device__ float g_Hp[B_ * NCH * D_];

DEV uint32_t smem_u32(const void* p) {
    uint32_t a;
    asm("{ .reg .u64 t; cvta.to.shared.u64 t, %1; cvt.u32.u64 %0, t; }" : "=r"(a) : "l"(p));
    return a;
}

#define CP16(dst, src) \
    asm volatile("cp.async.cg.shared.global [%0], [%1], 16;" :: "r"(dst), "l"(src) : "memory")
#define CP_COMMIT() asm volatile("cp.async.commit_group;" ::: "memory")
#define CP_WAIT(N)  asm volatile("cp.async.wait_group %0;" :: "n"(N) : "memory")

#define LDSM4(r0, r1, r2, r3, addr) \
    asm volatile("ldmatrix.sync.aligned.m8n8.x4.shared.b16 {%0,%1,%2,%3}, [%4];" \
        : "=r"(r0), "=r"(r1), "=r"(r2), "=r"(r3) : "r"(addr))

#define MMA(d, a0, a1, a2, a3, b0, b1) \
    asm volatile("mma.sync.aligned.m16n8k16.row.col.f32.f16.f16.f32 " \
        "{%0,%1,%2,%3}, {%4,%5,%6,%7}, {%8,%9}, {%0,%1,%2,%3};" \
        : "+f"((d)[0]), "+f"((d)[1]), "+f"((d)[2]), "+f"((d)[3]) \
        : "r"(a0), "r"(a1), "r"(a2), "r"(a3), "r"(b0), "r"(b1))

// ---------------- K0a: x fp32 -> fp16 ----------------
__global__ void k_cvt_x(const float4* __restrict__ x4) {
    size_t i = (size_t)blockIdx.x * blockDim.x + threadIdx.x;
    if (i < (size_t)BT * D_ / 4) {
        float4 v = x4[i];
        __half2 h0 = __floats2half2_rn(v.x, v.y);
        __half2 h1 = __floats2half2_rn(v.z, v.w);
        uint2 u;
        u.x = *reinterpret_cast<uint32_t*>(&h0);
        u.y = *reinterpret_cast<uint32_t*>(&h1);
        reinterpret_cast<uint2*>(g_xh)[i] = u;
    }
}

// ---------------- K0b: W[D,2D] -> W^T fp16 [2D,D] ----------------
__global__ void k_wt(const float* __restrict__ W) {
    __shared__ float tile[32][33];
    int e0 = blockIdx.x * 32, d0 = blockIdx.y * 32;
    int tx = threadIdx.x, ty = threadIdx.y;
#pragma unroll
    for (int j = 0; j < 4; ++j)
        tile[ty + 8 * j][tx] = W[(size_t)(d0 + ty + 8 * j) * N2 + e0 + tx];
    __syncthreads();
#pragma unroll
    for (int j = 0; j < 4; ++j)
        g_wt[(size_t)(e0 + ty + 8 * j) * D_ + d0 + tx] = __float2half_rn(tile[tx][ty + 8 * j]);
}

// ---------------- K1: HMMA GEMM + gate epilogue + fused local scan ----------------
static constexpr int ROWB   = 80;              // smem bytes per 32-half row (padded)
static constexpr int TILE_B = 128 * ROWB;      // 10240 B per operand tile
static constexpr int NBUF   = 4;
static constexpr int SMEM_PIPE = NBUF * 2 * TILE_B;        // 81920
static constexpr int SMEM_EPI  = 2 * 128 * 72 * 4 + 2048;  // staging + seg aggregates
static constexpr int SMEM_DYN  = (SMEM_PIPE > SMEM_EPI) ? SMEM_PIPE : SMEM_EPI;

DEV void gate(float ht, float kk, float& c, float& v) {
    float ek = __expf(kk);
    c = 1.f / (1.f + ek);                   // sigmoid(-k) = exp(log_coeffs)
    float z = 1.f - c;                      // sigmoid(k)
    float g = (ht >= 0.f) ? (ht + 0.5f) : (1.f / (1.f + __expf(-ht)));
    v = z * g;
}

DEV void load_tile(uint32_t sb, int kt, int buf, int m0, int j0, int tid) {
    uint32_t Ab = sb + (uint32_t)buf * (2 * TILE_B);
    uint32_t Bb = Ab + TILE_B;
#pragma unroll
    for (int i = 0; i < 2; ++i) {
        int ch = tid + 256 * i;
        int r = ch >> 2, cth = ch & 3;
        const __half* s = g_xh + (size_t)(m0 + r) * D_ + kt * 32 + cth * 8;
        CP16(Ab + (uint32_t)r * ROWB + cth * 16, s);
    }
#pragma unroll
    for (int i = 0; i < 2; ++i) {
        int ch = tid + 256 * i;
        int r = ch >> 2, cth = ch & 3;
        int e = (r < 64) ? (j0 + r) : (1024 + j0 + r - 64);
        const __half* s = g_wt + (size_t)e * D_ + kt * 32 + cth * 8;
        CP16(Bb + (uint32_t)r * ROWB + cth * 16, s);
    }
}

__global__ void __launch_bounds__(256) k_gemm(const float* __restrict__ bias) {
    extern __shared__ char smem[];
    uint32_t sb = smem_u32(smem);
    int tid = threadIdx.x;
    int wid = tid >> 5, lane = tid & 31;
    int wm = wid & 3, wn = wid >> 2;       // 4m x 2n warp grid; warp tile m32 x n64
    int m0 = blockIdx.y * 128;
    int j0 = blockIdx.x * 64;

    float acc[2][8][4] = {};               // [m16 tile][n8 tile][frag]

    load_tile(sb, 0, 0, m0, j0, tid); CP_COMMIT();
    load_tile(sb, 1, 1, m0, j0, tid); CP_COMMIT();

    uint32_t aoffB = (uint32_t)(lane & 15) * ROWB + (uint32_t)((lane >> 4) << 4);
    uint32_t boff  = (uint32_t)(((lane & 7) | ((lane >> 4) << 3))) * ROWB
                   + (uint32_t)(((lane >> 3) & 1) << 4);

#pragma unroll 1
    for (int kt = 0; kt < 32; ++kt) {
        if (kt + 2 < 32) { load_tile(sb, kt + 2, (kt + 2) & 3, m0, j0, tid); CP_COMMIT(); }
        if (kt < 30)      CP_WAIT(2);
        else if (kt == 30) CP_WAIT(1);
        else               CP_WAIT(0);
        __syncthreads();

        uint32_t Ab = sb + (uint32_t)(kt & 3) * (2 * TILE_B);
        uint32_t Bb = Ab + TILE_B;
#pragma unroll
        for (int s = 0; s < 2; ++s) {
            uint32_t a[2][4];
#pragma unroll
            for (int mi = 0; mi < 2; ++mi)
                LDSM4(a[mi][0], a[mi][1], a[mi][2], a[mi][3],
                      Ab + (uint32_t)(wm * 32 + mi * 16) * ROWB + aoffB + s * 32);
#pragma unroll
            for (int ni = 0; ni < 4; ++ni) {
                uint32_t b0, b1, b2, b3;
                LDSM4(b0, b1, b2, b3,
                      Bb + (uint32_t)(wn * 64 + ni * 16) * ROWB + boff + s * 32);
#pragma unroll
                for (int mi = 0; mi < 2; ++mi) {
                    MMA(acc[mi][2 * ni],     a[mi][0], a[mi][1], a[mi][2], a[mi][3], b0, b1);
                    MMA(acc[mi][2 * ni + 1], a[mi][0], a[mi][1], a[mi][2], a[mi][3], b2, b3);
                }
            }
        }
    }
    __syncthreads();   // pipeline drained; safe to reuse smem

    // ---- stage raw projections (+bias) into smem; wn=0 -> h~, wn=1 -> k ----
    float* hst = (float*)smem;           // 128 x 72
    float* kst = hst + 128 * 72;
    float* sA  = kst + 128 * 72;         // 256 seg aggregates
    float* sH  = sA + 256;
    {
        const float* bptr = bias + (wn ? (1024 + j0) : j0);
        float* dst = wn ? kst : hst;
        int rb = wm * 32 + (lane >> 2);
        int cb = (lane & 3) * 2;
#pragma unroll
        for (int mi = 0; mi < 2; ++mi) {
#pragma unroll
            for (int nj = 0; nj < 8; ++nj) {
                int r = rb + mi * 16;
                int c = nj * 8 + cb;
                float b0v = bptr[c], b1v = bptr[c + 1];
                dst[r * 72 + c]           = acc[mi][nj][0] + b0v;
                dst[r * 72 + c + 1]       = acc[mi][nj][1] + b1v;
                dst[(r + 8) * 72 + c]     = acc[mi][nj][2] + b0v;
                dst[(r + 8) * 72 + c + 1] = acc[mi][nj][3] + b1v;
            }
        }
    }
    __syncthreads();

    // ---- elementwise gate in place: hst <- c, kst <- v ----
#pragma unroll 4
    for (int i = 0; i < 32; ++i) {
        int e = i * 256 + tid;
        int r = e >> 6, c = e & 63;
        float cc, vv;
        gate(hst[r * 72 + c], kst[r * 72 + c], cc, vv);
        hst[r * 72 + c] = cc;
        kst[r * 72 + c] = vv;
    }
    __syncthreads();

    // fused local scan, phase 1: each thread scans 32 rows of one d-column
    {
        int seg  = tid >> 6;            // (chunk<<1)|half
        int dcol = tid & 63;
        int rs = seg * 32;
        float a = 1.f, h = 0.f;
#pragma unroll 8
        for (int t = 0; t < 32; ++t) {
            float c = hst[(rs + t) * 72 + dcol];
            float v = kst[(rs + t) * 72 + dcol];
            h = fmaf(c, h, v);
            a *= c;
        }
        sA[tid] = a; sH[tid] = h;
    }

    // coalesced fp16 stores of c/v (reads only hst/kst; no extra sync needed)
#pragma unroll
    for (int i = 0; i < 8; ++i) {
        int e = i * 256 + tid;
        int r = e >> 4, q = e & 15;
        size_t go = (size_t)(m0 + r) * D_ + j0 + q * 4;
        float4 cf = *(float4*)(hst + r * 72 + q * 4);
        float4 vf = *(float4*)(kst + r * 72 + q * 4);
        __half2 ca = __floats2half2_rn(cf.x, cf.y), cbh = __floats2half2_rn(cf.z, cf.w);
        __half2 va = __floats2half2_rn(vf.x, vf.y), vb = __floats2half2_rn(vf.z, vf.w);
        uint2 cu, vu;
        cu.x = *(uint32_t*)&ca; cu.y = *(uint32_t*)&cbh;
        vu.x = *(uint32_t*)&va; vu.y = *(uint32_t*)&vb;
        *(uint2*)(g_ch + go) = cu;
        *(uint2*)(g_vh + go) = vu;
    }
    __syncthreads();

    // fused local scan, phase 2: combine halves -> chunk aggregates
    if (tid < 128) {
        int chunk = tid >> 6, dcol = tid & 63;
        float aLo = sA[chunk * 128 + dcol],      hLo = sH[chunk * 128 + dcol];
        float aHi = sA[chunk * 128 + 64 + dcol], hHi = sH[chunk * 128 + 64 + dcol];
        int bc = (m0 >> 6) + chunk;
        g_A [bc * D_ + j0 + dcol] = aLo * aHi;
        g_Hl[bc * D_ + j0 + dcol] = fmaf(aHi, hLo, hHi);
    }
}

// ---------------- K3: cross-chunk prefix, warp Kogge-Stone ----------------
// one warp per (b,d); lane handles chunks 2*lane, 2*lane+1
__global__ void __launch_bounds__(256) k_scan2() {
    int t = blockIdx.x * blockDim.x + threadIdx.x;
    int w = t >> 5;                    // (b,d) index
    int lane = t & 31;
    int b = w >> 10, d = w & (D_ - 1);
    int bc0 = b * NCH + lane * 2;
    float a0 = g_A [bc0 * D_ + d];
    float h0 = g_Hl[bc0 * D_ + d];
    float a1 = g_A [(bc0 + 1) * D_ + d];
    float h1 = g_Hl[(bc0 + 1) * D_ + d];
    // combine pair: chunk0 then chunk1
    float ia = a0 * a1;
    float ih = fmaf(a1, h0, h1);
    // inclusive warp scan of affine ops (older applied first)
#pragma unroll
    for (int off = 1; off < 32; off <<= 1) {
        float ao = __shfl_up_sync(~0u, ia, off);
        float ho = __shfl_up_sync(~0u, ih, off);
        if (lane >= off) {
            ih = fmaf(ia, ho, ih);
            ia = ia * ao;
        }
    }
    // exclusive prefix entering chunk 2*lane
    float eh = __shfl_up_sync(~0u, ih, 1);
    if (lane == 0) eh = 0.f;
    g_Hp[bc0 * D_ + d]       = eh;
    g_Hp[(bc0 + 1) * D_ + d] = fmaf(a0, eh, h0);
}

// ---------------- K4: replay + residual + fused LayerNorm ----------------
__global__ void __launch_bounds__(512) k_scan3(const float* __restrict__ x,
        const float* __restrict__ gamma, const float* __restrict__ beta,
        float* __restrict__ out) {
    __shared__ float red[16];
    __shared__ float s_mu, s_rs;
    int bc = blockIdx.x;
    int tid = threadIdx.x;
    int lane = tid & 31, wrp = tid >> 5;
    int d2 = tid * 2;
    float h0 = g_Hp[bc * D_ + d2];
    float h1 = g_Hp[bc * D_ + d2 + 1];
    float2 ga = *(const float2*)(gamma + d2);
    float2 be = *(const float2*)(beta + d2);
    size_t base = (size_t)bc * CL * D_ + d2;
#pragma unroll 1
    for (int t = 0; t < CL; ++t) {
        size_t idx = base + (size_t)t * D_;
        __half2 c2 = *(const __half2*)(g_ch + idx);
        __half2 v2 = *(const __half2*)(g_vh + idx);
        float2 cf = __half22float2(c2);
        float2 vf = __half22float2(v2);
        h0 = fmaf(cf.x, h0, vf.x);
        h1 = fmaf(cf.y, h1, vf.y);
        float2 xx = *(const float2*)(x + idx);
        float y0 = xx.x + h0, y1 = xx.y + h1;
        float s = y0 + y1;
#pragma unroll
        for (int o = 16; o; o >>= 1) s += __shfl_xor_sync(~0u, s, o);
        if (lane == 0) red[wrp] = s;
        __syncthreads();
        if (wrp == 0) {
            float v = (lane < 16) ? red[lane] : 0.f;
#pragma unroll
            for (int o = 8; o; o >>= 1) v += __shfl_xor_sync(~0u, v, o);
            if (lane == 0) s_mu = v * (1.f / 1024.f);
        }
        __syncthreads();
        float mu = s_mu;
        float dy0 = y0 - mu, dy1 = y1 - mu;
        float q = dy0 * dy0 + dy1 * dy1;
#pragma unroll
        for (int o = 16; o; o >>= 1) q += __shfl_xor_sync(~0u, q, o);
        if (lane == 0) red[wrp] = q;
        __syncthreads();
        if (wrp == 0) {
            float v = (lane < 16) ? red[lane] : 0.f;
#pragma unroll
            for (int o = 8; o; o >>= 1) v += __shfl_xor_sync(~0u, v, o);
            if (lane == 0) s_rs = rsqrtf(v * (1.f / 1024.f) + LN_EPS);
        }
        __syncthreads();
        float rs = s_rs;
        float2 o2;
        o2.x = dy0 * rs * ga.x + be.x;
        o2.y = dy1 * rs * ga.y + be.y;
        *(float2*)(out + idx) = o2;
    }
}

extern "C" void kernel_launch(void* const* d_in, const int* in_sizes, int n_in,
                              void* d_out, int out_size) {
    const float* x     = (const float*)d_in[0];
    const float* W     = (const float*)d_in[1];
    const float* b     = (const float*)d_in[2];
    const float* gamma = (const float*)d_in[3];
    const float* beta  = (const float*)d_in[4];
    float* out = (float*)d_out;

    cudaFuncSetAttribute(k_gemm, cudaFuncAttributeMaxDynamicSharedMemorySize, SMEM_DYN);

    k_cvt_x<<<(BT * (D_ / 4) + 255) / 256, 256>>>((const float4*)x);
    k_wt<<<dim3(N2 / 32, D_ / 32), dim3(32, 8)>>>(W);
    k_gemm<<<dim3(D_ / 64, BT / 128), 256, SMEM_DYN>>>(b);
    k_scan2<<<(B_ * D_ * 32) / 256, 256>>>();
    k_scan3<<<B_ * NCH, 512>>>(x, gamma, beta, out);
}

// round 6
// speedup vs baseline: 1.5706x; 1.1809x over previous
#include <cuda_runtime.h>
#include <cuda_fp16.h>
#include <cstdint>

#define DEV __device__ __forceinline__

static constexpr int B_  = 8;
static constexpr int T_  = 4096;
static constexpr int D_  = 1024;
static constexpr int BT  = B_ * T_;        // 32768
static constexpr int N2  = 2 * D_;         // 2048
static constexpr int NCH = 64;
static constexpr int CL  = T_ / NCH;       // 64
static constexpr float LN_EPS = 1e-6f;

// pre-tiled operands: tile (blk, kt) = contiguous 4096 halves (8KB)
// element (row r 0..127, k-half kk 0..31): granule j=kk>>3, b=kk&7
// offset = ((blk*32+kt)*128 + r)*32 + ((j + (r>>1))&3)*8 + b   [halves]
__device__ __align__(16) __half g_xh[(size_t)BT * D_];   // x tiled fp16
__device__ __align__(16) __half g_wt[(size_t)N2 * D_];   // W^T tiled fp16
__device__ __align__(16) __half g_ch[(size_t)BT * D_];   // gate coeff (fp16, flat)
__device__ __align__(16) __half g_vh[(size_t)BT * D_];   // gate value (fp16, flat)
__device__ float g_A [B_ * NCH * D_];
__device__ float g_Hl[B_ * NCH * D_];
__device__ float g_Hp[B_ * NCH * D_];

DEV uint32_t smem_u32(const void* p) {
    uint32_t a;
    asm("{ .reg .u64 t; cvta.to.shared.u64 t, %1; cvt.u32.u64 %0, t; }" : "=r"(a) : "l"(p));
    return a;
}

#define MBAR_INIT(a, c) \
    asm volatile("mbarrier.init.shared.b64 [%0], %1;" :: "r"((uint32_t)(a)), "r"((uint32_t)(c)) : "memory")
#define MBAR_EXPECT_TX(a, tx) \
    asm volatile("mbarrier.arrive.expect_tx.shared.b64 _, [%0], %1;" :: "r"((uint32_t)(a)), "r"((uint32_t)(tx)) : "memory")
#define MBAR_WAIT(a, par) do {                                                             \
    uint32_t _m = (uint32_t)(a); uint32_t _p = (uint32_t)(par); uint32_t _d;               \
    asm volatile("{\n\t.reg .pred p;\n\t"                                                  \
        "mbarrier.try_wait.parity.acquire.cta.shared::cta.b64 p, [%1], %2;\n\t"            \
        "selp.b32 %0, 1, 0, p;\n\t}" : "=r"(_d) : "r"(_m), "r"(_p) : "memory");            \
    if (!_d) {                                                                             \
        asm volatile("{\n\t.reg .pred P1;\n\t"                                             \
            "WL_%=:\n\t"                                                                   \
            "mbarrier.try_wait.parity.acquire.cta.shared::cta.b64 P1, [%0], %1, 0x989680;\n\t" \
            "@P1 bra.uni WD_%=;\n\t bra.uni WL_%=;\n\t WD_%=:\n\t}"                        \
            :: "r"(_m), "r"(_p) : "memory");                                               \
    } } while (0)
#define BULK_G2S(dst, src, bytes, mbar) \
    asm volatile("cp.async.bulk.shared::cta.global.mbarrier::complete_tx::bytes [%0], [%1], %2, [%3];" \
        :: "r"((uint32_t)(dst)), "l"(src), "r"((uint32_t)(bytes)), "r"((uint32_t)(mbar)) : "memory")
#define FENCE_ASYNC() asm volatile("fence.proxy.async.shared::cta;" ::: "memory")

#define LDSM4(r0, r1, r2, r3, addr) \
    asm volatile("ldmatrix.sync.aligned.m8n8.x4.shared.b16 {%0,%1,%2,%3}, [%4];" \
        : "=r"(r0), "=r"(r1), "=r"(r2), "=r"(r3) : "r"(addr))

#define MMA(d, a0, a1, a2, a3, b0, b1) \
    asm volatile("mma.sync.aligned.m16n8k16.row.col.f32.f16.f16.f32 " \
        "{%0,%1,%2,%3}, {%4,%5,%6,%7}, {%8,%9}, {%0,%1,%2,%3};" \
        : "+f"((d)[0]), "+f"((d)[1]), "+f"((d)[2]), "+f"((d)[3]) \
        : "r"(a0), "r"(a1), "r"(a2), "r"(a3), "r"(b0), "r"(b1))

// ---------------- K0a: x fp32 -> fp16, tiled+swizzled ----------------
__global__ void __launch_bounds__(256) k_cvt_x(const float4* __restrict__ x4) {
    int g = blockIdx.x * blockDim.x + threadIdx.x;       // 16-byte granule id
    if (g >= BT * 128) return;
    int m = g >> 7, gk = g & 127;
    int kt = gk >> 2, j = gk & 3;
    float4 v0 = x4[(size_t)g * 2];
    float4 v1 = x4[(size_t)g * 2 + 1];
    __half2 h0 = __floats2half2_rn(v0.x, v0.y), h1 = __floats2half2_rn(v0.z, v0.w);
    __half2 h2 = __floats2half2_rn(v1.x, v1.y), h3 = __floats2half2_rn(v1.z, v1.w);
    uint4 u;
    u.x = *(uint32_t*)&h0; u.y = *(uint32_t*)&h1;
    u.z = *(uint32_t*)&h2; u.w = *(uint32_t*)&h3;
    int r = m & 127;
    size_t off = ((size_t)((m >> 7) * 32 + kt) * 128 + r) * 32
               + (size_t)(((j + (r >> 1)) & 3) * 8);
    *(uint4*)(g_xh + off) = u;
}

// ---------------- K0b: W[D,2D] -> W^T fp16, tiled+swizzled ----------------
// jblk pairs rows: e in [j*64, j*64+64) -> rowIn 0..63 ; e in [1024+j*64, ...) -> rowIn 64..127
__global__ void k_wt(const float* __restrict__ W) {
    __shared__ float tile[32][33];
    int e0 = blockIdx.x * 32, d0 = blockIdx.y * 32;
    int tx = threadIdx.x, ty = threadIdx.y;
#pragma unroll
    for (int jj = 0; jj < 4; ++jj)
        tile[ty + 8 * jj][tx] = W[(size_t)(d0 + ty + 8 * jj) * N2 + e0 + tx];
    __syncthreads();
#pragma unroll
    for (int jj = 0; jj < 4; ++jj) {
        int e = e0 + ty + 8 * jj;
        int d = d0 + tx;
        int jblk  = (e < 1024) ? (e >> 6) : ((e - 1024) >> 6);
        int rowIn = (e < 1024) ? (e & 63) : (64 + (e & 63));
        int kt = d >> 5, kk = d & 31;
        int jg = kk >> 3, bb = kk & 7;
        size_t off = ((size_t)(jblk * 32 + kt) * 128 + rowIn) * 32
                   + (size_t)(((jg + (rowIn >> 1)) & 3) * 8 + bb);
        g_wt[off] = __float2half_rn(tile[tx][ty + 8 * jj]);
    }
}

// ---------------- K1: HMMA GEMM (bulk-copy pipeline) + gates + local scan ----------------
static constexpr int SLOT_B   = 16384;               // A 8KB + B 8KB per kt
static constexpr int NBUF     = 4;
static constexpr int MBAR_OFF = NBUF * SLOT_B;       // 65536
static constexpr int SMEM_EPI = 2 * 128 * 72 * 4 + 2048;
static constexpr int SMEM_DYN = (MBAR_OFF + 64 > SMEM_EPI) ? (MBAR_OFF + 64) : SMEM_EPI;

DEV void gate(float ht, float kk, float& c, float& v) {
    float ek = __expf(kk);
    c = 1.f / (1.f + ek);                   // sigmoid(-k)
    float z = 1.f - c;                      // sigmoid(k)
    float g = (ht >= 0.f) ? (ht + 0.5f) : (1.f / (1.f + __expf(-ht)));
    v = z * g;
}

__global__ void __launch_bounds__(256) k_gemm(const float* __restrict__ bias) {
    extern __shared__ char smem[];
    uint32_t sb = smem_u32(smem);
    int tid = threadIdx.x;
    int wid = tid >> 5, lane = tid & 31;
    int wm = wid & 3, wn = wid >> 2;        // 4m x 2n warp grid, warp tile m32 x n64
    int mt = blockIdx.y;                    // m-tile (128 rows)
    int jb = blockIdx.x;                    // j block (64 pairs)
    int m0 = mt * 128, j0 = jb * 64;

    const __half* Asrc = g_xh + (size_t)mt * 32 * 4096;
    const __half* Bsrc = g_wt + (size_t)jb * 32 * 4096;

    if (tid == 0) {
#pragma unroll
        for (int s = 0; s < NBUF; ++s) MBAR_INIT(sb + MBAR_OFF + 8 * s, 1);
        FENCE_ASYNC();
    }
    __syncthreads();
    if (tid == 0) {
#pragma unroll
        for (int kt = 0; kt < 2; ++kt) {
            uint32_t mb = sb + MBAR_OFF + 8 * kt;
            MBAR_EXPECT_TX(mb, 16384);
            BULK_G2S(sb + kt * SLOT_B,        Asrc + (size_t)kt * 4096, 8192, mb);
            BULK_G2S(sb + kt * SLOT_B + 8192, Bsrc + (size_t)kt * 4096, 8192, mb);
        }
    }

    float acc[2][8][4] = {};

    // ldmatrix lane addressing (swizzled tiled layout)
    int la15 = lane & 15, lhi = lane >> 4;
    int rA = wm * 32 + la15;
    uint32_t aRow = (uint32_t)rA * 64;
    uint32_t aCol0 = (uint32_t)(((lhi + (rA >> 1)) & 3) << 4);          // s=0
    int rB = wn * 64 + ((lane & 7) | (lhi << 3));
    uint32_t bRow = (uint32_t)rB * 64;
    uint32_t bCol0 = (uint32_t)(((((lane >> 3) & 1) + (rB >> 1)) & 3) << 4);

#pragma unroll 1
    for (int kt = 0; kt < 32; ++kt) {
        __syncthreads();                     // all done reading slot (kt+2)&3's old data
        if (tid == 0 && kt + 2 < 32) {
            int sl = (kt + 2) & 3;
            uint32_t mb = sb + MBAR_OFF + 8 * sl;
            MBAR_EXPECT_TX(mb, 16384);
            BULK_G2S(sb + sl * SLOT_B,        Asrc + (size_t)(kt + 2) * 4096, 8192, mb);
            BULK_G2S(sb + sl * SLOT_B + 8192, Bsrc + (size_t)(kt + 2) * 4096, 8192, mb);
        }
        MBAR_WAIT(sb + MBAR_OFF + 8 * (kt & 3), (kt >> 2) & 1);

        uint32_t Ab = sb + (uint32_t)(kt & 3) * SLOT_B;
        uint32_t Bb = Ab + 8192;
#pragma unroll
        for (int s = 0; s < 2; ++s) {
            uint32_t aCol = aCol0 ^ (s << 5);
            uint32_t bCol = bCol0 ^ (s << 5);
            uint32_t a[2][4];
#pragma unroll
            for (int mi = 0; mi < 2; ++mi)
                LDSM4(a[mi][0], a[mi][1], a[mi][2], a[mi][3],
                      Ab + aRow + (uint32_t)mi * 1024 + aCol);
#pragma unroll
            for (int ni = 0; ni < 4; ++ni) {
                uint32_t b0, b1, b2, b3;
                LDSM4(b0, b1, b2, b3, Bb + bRow + (uint32_t)ni * 1024 + bCol);
#pragma unroll
                for (int mi = 0; mi < 2; ++mi) {
                    MMA(acc[mi][2 * ni],     a[mi][0], a[mi][1], a[mi][2], a[mi][3], b0, b1);
                    MMA(acc[mi][2 * ni + 1], a[mi][0], a[mi][1], a[mi][2], a[mi][3], b2, b3);
                }
            }
        }
    }
    __syncthreads();   // drained; reuse smem for epilogue

    // ---- stage raw projections (+bias); wn=0 -> h~, wn=1 -> k ----
    float* hst = (float*)smem;           // 128 x 72
    float* kst = hst + 128 * 72;
    float* sA  = kst + 128 * 72;         // 256 seg aggregates
    float* sH  = sA + 256;
    {
        const float* bptr = bias + (wn ? (1024 + j0) : j0);
        float* dst = wn ? kst : hst;
        int rb = wm * 32 + (lane >> 2);
        int cb = (lane & 3) * 2;
#pragma unroll
        for (int mi = 0; mi < 2; ++mi) {
#pragma unroll
            for (int nj = 0; nj < 8; ++nj) {
                int r = rb + mi * 16;
                int c = nj * 8 + cb;
                float b0v = bptr[c], b1v = bptr[c + 1];
                dst[r * 72 + c]           = acc[mi][nj][0] + b0v;
                dst[r * 72 + c + 1]       = acc[mi][nj][1] + b1v;
                dst[(r + 8) * 72 + c]     = acc[mi][nj][2] + b0v;
                dst[(r + 8) * 72 + c + 1] = acc[mi][nj][3] + b1v;
            }
        }
    }
    __syncthreads();

    // ---- elementwise gate in place: hst <- c, kst <- v ----
#pragma unroll 4
    for (int i = 0; i < 32; ++i) {
        int e = i * 256 + tid;
        int r = e >> 6, c = e & 63;
        float cc, vv;
        gate(hst[r * 72 + c], kst[r * 72 + c], cc, vv);
        hst[r * 72 + c] = cc;
        kst[r * 72 + c] = vv;
    }
    __syncthreads();

    // fused local scan, phase 1: each thread scans 32 rows of one d-column
    {
        int seg  = tid >> 6;            // (chunk<<1)|half
        int dcol = tid & 63;
        int rs = seg * 32;
        float a = 1.f, h = 0.f;
#pragma unroll 8
        for (int t = 0; t < 32; ++t) {
            float c = hst[(rs + t) * 72 + dcol];
            float v = kst[(rs + t) * 72 + dcol];
            h = fmaf(c, h, v);
            a *= c;
        }
        sA[tid] = a; sH[tid] = h;
    }

    // coalesced fp16 stores of c/v (flat layout)
#pragma unroll
    for (int i = 0; i < 8; ++i) {
        int e = i * 256 + tid;
        int r = e >> 4, q = e & 15;
        size_t go = (size_t)(m0 + r) * D_ + j0 + q * 4;
        float4 cf = *(float4*)(hst + r * 72 + q * 4);
        float4 vf = *(float4*)(kst + r * 72 + q * 4);
        __half2 ca = __floats2half2_rn(cf.x, cf.y), cbh = __floats2half2_rn(cf.z, cf.w);
        __half2 va = __floats2half2_rn(vf.x, vf.y), vb = __floats2half2_rn(vf.z, vf.w);
        uint2 cu, vu;
        cu.x = *(uint32_t*)&ca; cu.y = *(uint32_t*)&cbh;
        vu.x = *(uint32_t*)&va; vu.y = *(uint32_t*)&vb;
        *(uint2*)(g_ch + go) = cu;
        *(uint2*)(g_vh + go) = vu;
    }
    __syncthreads();

    // local scan, phase 2: combine halves -> chunk aggregates
    if (tid < 128) {
        int chunk = tid >> 6, dcol = tid & 63;
        float aLo = sA[chunk * 128 + dcol],      hLo = sH[chunk * 128 + dcol];
        float aHi = sA[chunk * 128 + 64 + dcol], hHi = sH[chunk * 128 + 64 + dcol];
        int bc = (m0 >> 6) + chunk;
        g_A [bc * D_ + j0 + dcol] = aLo * aHi;
        g_Hl[bc * D_ + j0 + dcol] = fmaf(aHi, hLo, hHi);
    }
}

// ---------------- K3: cross-chunk prefix, warp Kogge-Stone ----------------
__global__ void __launch_bounds__(256) k_scan2() {
    int t = blockIdx.x * blockDim.x + threadIdx.x;
    int w = t >> 5;
    int lane = t & 31;
    int b = w >> 10, d = w & (D_ - 1);
    int bc0 = b * NCH + lane * 2;
    float a0 = g_A [bc0 * D_ + d];
    float h0 = g_Hl[bc0 * D_ + d];
    float a1 = g_A [(bc0 + 1) * D_ + d];
    float h1 = g_Hl[(bc0 + 1) * D_ + d];
    float ia = a0 * a1;
    float ih = fmaf(a1, h0, h1);
#pragma unroll
    for (int off = 1; off < 32; off <<= 1) {
        float ao = __shfl_up_sync(~0u, ia, off);
        float ho = __shfl_up_sync(~0u, ih, off);
        if (lane >= off) {
            ih = fmaf(ia, ho, ih);
            ia = ia * ao;
        }
    }
    float eh = __shfl_up_sync(~0u, ih, 1);
    if (lane == 0) eh = 0.f;
    g_Hp[bc0 * D_ + d]       = eh;
    g_Hp[(bc0 + 1) * D_ + d] = fmaf(a0, eh, h0);
}

// ---------------- K4: replay + residual + LayerNorm (2 timesteps / round) ----------------
__global__ void __launch_bounds__(512) k_scan3(const float* __restrict__ x,
        const float* __restrict__ gamma, const float* __restrict__ beta,
        float* __restrict__ out) {
    __shared__ float2 red[16];
    __shared__ float2 s_mu, s_rs;
    int bc = blockIdx.x;
    int tid = threadIdx.x;
    int lane = tid & 31, wrp = tid >> 5;
    int d2 = tid * 2;
    float h0 = g_Hp[bc * D_ + d2];
    float h1 = g_Hp[bc * D_ + d2 + 1];
    float2 ga = *(const float2*)(gamma + d2);
    float2 be = *(const float2*)(beta + d2);
    size_t base = (size_t)bc * CL * D_ + d2;
#pragma unroll 1
    for (int t = 0; t < CL; t += 2) {
        size_t i0 = base + (size_t)t * D_;
        size_t i1 = i0 + D_;
        float2 c0 = __half22float2(*(const __half2*)(g_ch + i0));
        float2 v0 = __half22float2(*(const __half2*)(g_vh + i0));
        float2 c1 = __half22float2(*(const __half2*)(g_ch + i1));
        float2 v1 = __half22float2(*(const __half2*)(g_vh + i1));
        float2 xa = *(const float2*)(x + i0);
        float2 xb = *(const float2*)(x + i1);
        h0 = fmaf(c0.x, h0, v0.x); h1 = fmaf(c0.y, h1, v0.y);
        float ya0 = xa.x + h0, ya1 = xa.y + h1;
        h0 = fmaf(c1.x, h0, v1.x); h1 = fmaf(c1.y, h1, v1.y);
        float yb0 = xb.x + h0, yb1 = xb.y + h1;

        float sx = ya0 + ya1, sy = yb0 + yb1;
#pragma unroll
        for (int o = 16; o; o >>= 1) {
            sx += __shfl_xor_sync(~0u, sx, o);
            sy += __shfl_xor_sync(~0u, sy, o);
        }
        if (lane == 0) red[wrp] = make_float2(sx, sy);
        __syncthreads();
        if (wrp == 0) {
            float2 v = (lane < 16) ? red[lane] : make_float2(0.f, 0.f);
#pragma unroll
            for (int o = 8; o; o >>= 1) {
                v.x += __shfl_xor_sync(~0u, v.x, o);
                v.y += __shfl_xor_sync(~0u, v.y, o);
            }
            if (lane == 0) s_mu = make_float2(v.x * (1.f / 1024.f), v.y * (1.f / 1024.f));
        }
        __syncthreads();
        float mua = s_mu.x, mub = s_mu.y;
        float da0 = ya0 - mua, da1 = ya1 - mua;
        float db0 = yb0 - mub, db1 = yb1 - mub;
        float qx = da0 * da0 + da1 * da1, qy = db0 * db0 + db1 * db1;
#pragma unroll
        for (int o = 16; o; o >>= 1) {
            qx += __shfl_xor_sync(~0u, qx, o);
            qy += __shfl_xor_sync(~0u, qy, o);
        }
        if (lane == 0) red[wrp] = make_float2(qx, qy);
        __syncthreads();
        if (wrp == 0) {
            float2 v = (lane < 16) ? red[lane] : make_float2(0.f, 0.f);
#pragma unroll
            for (int o = 8; o; o >>= 1) {
                v.x += __shfl_xor_sync(~0u, v.x, o);
                v.y += __shfl_xor_sync(~0u, v.y, o);
            }
            if (lane == 0) s_rs = make_float2(rsqrtf(v.x * (1.f / 1024.f) + LN_EPS),
                                              rsqrtf(v.y * (1.f / 1024.f) + LN_EPS));
        }
        __syncthreads();
        float rsa = s_rs.x, rsb = s_rs.y;
        float2 oa, ob;
        oa.x = da0 * rsa * ga.x + be.x;  oa.y = da1 * rsa * ga.y + be.y;
        ob.x = db0 * rsb * ga.x + be.x;  ob.y = db1 * rsb * ga.y + be.y;
        *(float2*)(out + i0) = oa;
        *(float2*)(out + i1) = ob;
    }
}

extern "C" void kernel_launch(void* const* d_in, const int* in_sizes, int n_in,
                              void* d_out, int out_size) {
    const float* x     = (const float*)d_in[0];
    const float* W     = (const float*)d_in[1];
    const float* b     = (const float*)d_in[2];
    const float* gamma = (const float*)d_in[3];
    const float* beta  = (const float*)d_in[4];
    float* out = (float*)d_out;

    cudaFuncSetAttribute(k_gemm, cudaFuncAttributeMaxDynamicSharedMemorySize, SMEM_DYN);

    k_cvt_x<<<(BT * 128) / 256, 256>>>((const float4*)x);
    k_wt<<<dim3(N2 / 32, D_ / 32), dim3(32, 8)>>>(W);
    k_gemm<<<dim3(D_ / 64, BT / 128), 256, SMEM_DYN>>>(b);
    k_scan2<<<(B_ * D_ * 32) / 256, 256>>>();
    k_scan3<<<B_ * NCH, 512>>>(x, gamma, beta, out);
}

// round 7
// speedup vs baseline: 1.6691x; 1.0627x over previous
#include <cuda_runtime.h>
#include <cuda_fp16.h>
#include <cstdint>

#define DEV __device__ __forceinline__

static constexpr int B_  = 8;
static constexpr int T_  = 4096;
static constexpr int D_  = 1024;
static constexpr int BT  = B_ * T_;        // 32768
static constexpr int N2  = 2 * D_;         // 2048
static constexpr int NCH = 64;
static constexpr int CL  = T_ / NCH;       // 64
static constexpr float LN_EPS = 1e-6f;

// pre-tiled operands: tile (blk, kt) = contiguous 4096 halves (8KB)
// element (row r 0..127, k-half kk 0..31): granule j=kk>>3, b=kk&7
// offset = ((blk*32+kt)*128 + r)*32 + ((j + (r>>1))&3)*8 + b   [halves]
__device__ __align__(16) __half g_xh[(size_t)BT * D_];   // x tiled fp16
__device__ __align__(16) __half g_wt[(size_t)N2 * D_];   // W^T tiled fp16
__device__ __align__(16) __half g_ch[(size_t)BT * D_];   // gate coeff (fp16, flat)
__device__ __align__(16) __half g_vh[(size_t)BT * D_];   // gate value (fp16, flat)
__device__ float g_A [B_ * NCH * D_];
__device__ float g_Hl[B_ * NCH * D_];
__device__ float g_Hp[B_ * NCH * D_];

DEV uint32_t smem_u32(const void* p) {
    uint32_t a;
    asm("{ .reg .u64 t; cvta.to.shared.u64 t, %1; cvt.u32.u64 %0, t; }" : "=r"(a) : "l"(p));
    return a;
}

#define MBAR_INIT(a, c) \
    asm volatile("mbarrier.init.shared.b64 [%0], %1;" :: "r"((uint32_t)(a)), "r"((uint32_t)(c)) : "memory")
#define MBAR_EXPECT_TX(a, tx) \
    asm volatile("mbarrier.arrive.expect_tx.shared.b64 _, [%0], %1;" :: "r"((uint32_t)(a)), "r"((uint32_t)(tx)) : "memory")
#define MBAR_WAIT(a, par) do {                                                             \
    uint32_t _m = (uint32_t)(a); uint32_t _p = (uint32_t)(par); uint32_t _d;               \
    asm volatile("{\n\t.reg .pred p;\n\t"                                                  \
        "mbarrier.try_wait.parity.acquire.cta.shared::cta.b64 p, [%1], %2;\n\t"            \
        "selp.b32 %0, 1, 0, p;\n\t}" : "=r"(_d) : "r"(_m), "r"(_p) : "memory");            \
    if (!_d) {                                                                             \
        asm volatile("{\n\t.reg .pred P1;\n\t"                                             \
            "WL_%=:\n\t"                                                                   \
            "mbarrier.try_wait.parity.acquire.cta.shared::cta.b64 P1, [%0], %1, 0x989680;\n\t" \
            "@P1 bra.uni WD_%=;\n\t bra.uni WL_%=;\n\t WD_%=:\n\t}"                        \
            :: "r"(_m), "r"(_p) : "memory");                                               \
    } } while (0)
#define BULK_G2S(dst, src, bytes, mbar) \
    asm volatile("cp.async.bulk.shared::cta.global.mbarrier::complete_tx::bytes [%0], [%1], %2, [%3];" \
        :: "r"((uint32_t)(dst)), "l"(src), "r"((uint32_t)(bytes)), "r"((uint32_t)(mbar)) : "memory")
#define FENCE_ASYNC() asm volatile("fence.proxy.async.shared::cta;" ::: "memory")

#define LDSM4(r0, r1, r2, r3, addr) \
    asm volatile("ldmatrix.sync.aligned.m8n8.x4.shared.b16 {%0,%1,%2,%3}, [%4];" \
        : "=r"(r0), "=r"(r1), "=r"(r2), "=r"(r3) : "r"(addr))

#define MMA(d, a0, a1, a2, a3, b0, b1) \
    asm volatile("mma.sync.aligned.m16n8k16.row.col.f32.f16.f16.f32 " \
        "{%0,%1,%2,%3}, {%4,%5,%6,%7}, {%8,%9}, {%0,%1,%2,%3};" \
        : "+f"((d)[0]), "+f"((d)[1]), "+f"((d)[2]), "+f"((d)[3]) \
        : "r"(a0), "r"(a1), "r"(a2), "r"(a3), "r"(b0), "r"(b1))

// ---------------- K0a: x fp32 -> fp16, tiled+swizzled ----------------
__global__ void __launch_bounds__(256) k_cvt_x(const float4* __restrict__ x4) {
    int g = blockIdx.x * blockDim.x + threadIdx.x;       // 16-byte granule id
    if (g >= BT * 128) return;
    int m = g >> 7, gk = g & 127;
    int kt = gk >> 2, j = gk & 3;
    float4 v0 = x4[(size_t)g * 2];
    float4 v1 = x4[(size_t)g * 2 + 1];
    __half2 h0 = __floats2half2_rn(v0.x, v0.y), h1 = __floats2half2_rn(v0.z, v0.w);
    __half2 h2 = __floats2half2_rn(v1.x, v1.y), h3 = __floats2half2_rn(v1.z, v1.w);
    uint4 u;
    u.x = *(uint32_t*)&h0; u.y = *(uint32_t*)&h1;
    u.z = *(uint32_t*)&h2; u.w = *(uint32_t*)&h3;
    int r = m & 127;
    size_t off = ((size_t)((m >> 7) * 32 + kt) * 128 + r) * 32
               + (size_t)(((j + (r >> 1)) & 3) * 8);
    *(uint4*)(g_xh + off) = u;
}

// ---------------- K0b: W[D,2D] -> W^T fp16, tiled+swizzled ----------------
__global__ void k_wt(const float* __restrict__ W) {
    __shared__ float tile[32][33];
    int e0 = blockIdx.x * 32, d0 = blockIdx.y * 32;
    int tx = threadIdx.x, ty = threadIdx.y;
#pragma unroll
    for (int jj = 0; jj < 4; ++jj)
        tile[ty + 8 * jj][tx] = W[(size_t)(d0 + ty + 8 * jj) * N2 + e0 + tx];
    __syncthreads();
#pragma unroll
    for (int jj = 0; jj < 4; ++jj) {
        int e = e0 + ty + 8 * jj;
        int d = d0 + tx;
        int jblk  = (e < 1024) ? (e >> 6) : ((e - 1024) >> 6);
        int rowIn = (e < 1024) ? (e & 63) : (64 + (e & 63));
        int kt = d >> 5, kk = d & 31;
        int jg = kk >> 3, bb = kk & 7;
        size_t off = ((size_t)(jblk * 32 + kt) * 128 + rowIn) * 32
                   + (size_t)(((jg + (rowIn >> 1)) & 3) * 8 + bb);
        g_wt[off] = __float2half_rn(tile[tx][ty + 8 * jj]);
    }
}

// ---------------- K1: HMMA GEMM (bulk-copy pipeline) + gates + local scan ----------------
static constexpr int SLOT_B   = 16384;               // A 8KB + B 8KB per kt
static constexpr int NBUF     = 4;
static constexpr int MBAR_OFF = NBUF * SLOT_B;       // 65536
static constexpr int SMEM_EPI = 2 * 128 * 72 * 4 + 2048;
static constexpr int SMEM_DYN = (MBAR_OFF + 64 > SMEM_EPI) ? (MBAR_OFF + 64) : SMEM_EPI;

DEV void gate(float ht, float kk, float& c, float& v) {
    float ek = __expf(kk);
    c = 1.f / (1.f + ek);                   // sigmoid(-k)
    float z = 1.f - c;                      // sigmoid(k)
    float g = (ht >= 0.f) ? (ht + 0.5f) : (1.f / (1.f + __expf(-ht)));
    v = z * g;
}

__global__ void __launch_bounds__(256) k_gemm(const float* __restrict__ bias) {
    extern __shared__ char smem[];
    uint32_t sb = smem_u32(smem);
    int tid = threadIdx.x;
    int wid = tid >> 5, lane = tid & 31;
    int wm = wid & 3, wn = wid >> 2;        // 4m x 2n warp grid, warp tile m32 x n64
    int mt = blockIdx.y;                    // m-tile (128 rows)
    int jb = blockIdx.x;                    // j block (64 pairs)
    int m0 = mt * 128, j0 = jb * 64;

    const __half* Asrc = g_xh + (size_t)mt * 32 * 4096;
    const __half* Bsrc = g_wt + (size_t)jb * 32 * 4096;

    if (tid == 0) {
#pragma unroll
        for (int s = 0; s < NBUF; ++s) MBAR_INIT(sb + MBAR_OFF + 8 * s, 1);
        FENCE_ASYNC();
    }
    __syncthreads();
    if (tid == 0) {
#pragma unroll
        for (int kt = 0; kt < 2; ++kt) {
            uint32_t mb = sb + MBAR_OFF + 8 * kt;
            MBAR_EXPECT_TX(mb, 16384);
            BULK_G2S(sb + kt * SLOT_B,        Asrc + (size_t)kt * 4096, 8192, mb);
            BULK_G2S(sb + kt * SLOT_B + 8192, Bsrc + (size_t)kt * 4096, 8192, mb);
        }
    }

    float acc[2][8][4] = {};

    // ldmatrix lane addressing (swizzled tiled layout)
    int la15 = lane & 15, lhi = lane >> 4;
    int rA = wm * 32 + la15;
    uint32_t aRow = (uint32_t)rA * 64;
    uint32_t aCol0 = (uint32_t)(((lhi + (rA >> 1)) & 3) << 4);          // s=0
    int rB = wn * 64 + ((lane & 7) | (lhi << 3));
    uint32_t bRow = (uint32_t)rB * 64;
    uint32_t bCol0 = (uint32_t)(((((lane >> 3) & 1) + (rB >> 1)) & 3) << 4);

    // paired k-tiles: 1 sync per 2 kt; copies for (kt+2, kt+3) issued right
    // after the sync so they hide under ~2 k-tiles of compute. Slot (kt+2)&3
    // was last read in the previous iteration (ordered by this sync).
#pragma unroll 1
    for (int kt = 0; kt < 32; kt += 2) {
        __syncthreads();
        if (tid == 0 && kt + 2 < 32) {
#pragma unroll
            for (int q = 2; q < 4; ++q) {
                int sl = (kt + q) & 3;
                uint32_t mb = sb + MBAR_OFF + 8 * sl;
                MBAR_EXPECT_TX(mb, 16384);
                BULK_G2S(sb + sl * SLOT_B,        Asrc + (size_t)(kt + q) * 4096, 8192, mb);
                BULK_G2S(sb + sl * SLOT_B + 8192, Bsrc + (size_t)(kt + q) * 4096, 8192, mb);
            }
        }
#pragma unroll
        for (int q = 0; q < 2; ++q) {
            int ktq = kt + q;
            MBAR_WAIT(sb + MBAR_OFF + 8 * (ktq & 3), (ktq >> 2) & 1);
            uint32_t Ab = sb + (uint32_t)(ktq & 3) * SLOT_B;
            uint32_t Bb = Ab + 8192;
#pragma unroll
            for (int s = 0; s < 2; ++s) {
                uint32_t aCol = aCol0 ^ (s << 5);
                uint32_t bCol = bCol0 ^ (s << 5);
                uint32_t a[2][4];
#pragma unroll
                for (int mi = 0; mi < 2; ++mi)
                    LDSM4(a[mi][0], a[mi][1], a[mi][2], a[mi][3],
                          Ab + aRow + (uint32_t)mi * 1024 + aCol);
#pragma unroll
                for (int ni = 0; ni < 4; ++ni) {
                    uint32_t b0, b1, b2, b3;
                    LDSM4(b0, b1, b2, b3, Bb + bRow + (uint32_t)ni * 1024 + bCol);
#pragma unroll
                    for (int mi = 0; mi < 2; ++mi) {
                        MMA(acc[mi][2 * ni],     a[mi][0], a[mi][1], a[mi][2], a[mi][3], b0, b1);
                        MMA(acc[mi][2 * ni + 1], a[mi][0], a[mi][1], a[mi][2], a[mi][3], b2, b3);
                    }
                }
            }
        }
    }
    __syncthreads();   // drained; reuse smem for epilogue

    // ---- stage raw projections (+bias); wn=0 -> h~, wn=1 -> k ----
    float* hst = (float*)smem;           // 128 x 72
    float* kst = hst + 128 * 72;
    float* sA  = kst + 128 * 72;         // 256 seg aggregates
    float* sH  = sA + 256;
    {
        const float* bptr = bias + (wn ? (1024 + j0) : j0);
        float* dst = wn ? kst : hst;
        int rb = wm * 32 + (lane >> 2);
        int cb = (lane & 3) * 2;
#pragma unroll
        for (int mi = 0; mi < 2; ++mi) {
#pragma unroll
            for (int nj = 0; nj < 8; ++nj) {
                int r = rb + mi * 16;
                int c = nj * 8 + cb;
                float b0v = bptr[c], b1v = bptr[c + 1];
                dst[r * 72 + c]           = acc[mi][nj][0] + b0v;
                dst[r * 72 + c + 1]       = acc[mi][nj][1] + b1v;
                dst[(r + 8) * 72 + c]     = acc[mi][nj][2] + b0v;
                dst[(r + 8) * 72 + c + 1] = acc[mi][nj][3] + b1v;
            }
        }
    }
    __syncthreads();

    // ---- elementwise gate in place: hst <- c, kst <- v ----
#pragma unroll 4
    for (int i = 0; i < 32; ++i) {
        int e = i * 256 + tid;
        int r = e >> 6, c = e & 63;
        float cc, vv;
        gate(hst[r * 72 + c], kst[r * 72 + c], cc, vv);
        hst[r * 72 + c] = cc;
        kst[r * 72 + c] = vv;
    }
    __syncthreads();

    // fused local scan, phase 1: each thread scans 32 rows of one d-column
    {
        int seg  = tid >> 6;            // (chunk<<1)|half
        int dcol = tid & 63;
        int rs = seg * 32;
        float a = 1.f, h = 0.f;
#pragma unroll 8
        for (int t = 0; t < 32; ++t) {
            float c = hst[(rs + t) * 72 + dcol];
            float v = kst[(rs + t) * 72 + dcol];
            h = fmaf(c, h, v);
            a *= c;
        }
        sA[tid] = a; sH[tid] = h;
    }

    // coalesced fp16 stores of c/v (flat layout)
#pragma unroll
    for (int i = 0; i < 8; ++i) {
        int e = i * 256 + tid;
        int r = e >> 4, q = e & 15;
        size_t go = (size_t)(m0 + r) * D_ + j0 + q * 4;
        float4 cf = *(float4*)(hst + r * 72 + q * 4);
        float4 vf = *(float4*)(kst + r * 72 + q * 4);
        __half2 ca = __floats2half2_rn(cf.x, cf.y), cbh = __floats2half2_rn(cf.z, cf.w);
        __half2 va = __floats2half2_rn(vf.x, vf.y), vb = __floats2half2_rn(vf.z, vf.w);
        uint2 cu, vu;
        cu.x = *(uint32_t*)&ca; cu.y = *(uint32_t*)&cbh;
        vu.x = *(uint32_t*)&va; vu.y = *(uint32_t*)&vb;
        *(uint2*)(g_ch + go) = cu;
        *(uint2*)(g_vh + go) = vu;
    }
    __syncthreads();

    // local scan, phase 2: combine halves -> chunk aggregates
    if (tid < 128) {
        int chunk = tid >> 6, dcol = tid & 63;
        float aLo = sA[chunk * 128 + dcol],      hLo = sH[chunk * 128 + dcol];
        float aHi = sA[chunk * 128 + 64 + dcol], hHi = sH[chunk * 128 + 64 + dcol];
        int bc = (m0 >> 6) + chunk;
        g_A [bc * D_ + j0 + dcol] = aLo * aHi;
        g_Hl[bc * D_ + j0 + dcol] = fmaf(aHi, hLo, hHi);
    }
}

// ---------------- K3: cross-chunk prefix, warp Kogge-Stone ----------------
__global__ void __launch_bounds__(256) k_scan2() {
    int t = blockIdx.x * blockDim.x + threadIdx.x;
    int w = t >> 5;
    int lane = t & 31;
    int b = w >> 10, d = w & (D_ - 1);
    int bc0 = b * NCH + lane * 2;
    float a0 = g_A [bc0 * D_ + d];
    float h0 = g_Hl[bc0 * D_ + d];
    float a1 = g_A [(bc0 + 1) * D_ + d];
    float h1 = g_Hl[(bc0 + 1) * D_ + d];
    float ia = a0 * a1;
    float ih = fmaf(a1, h0, h1);
#pragma unroll
    for (int off = 1; off < 32; off <<= 1) {
        float ao = __shfl_up_sync(~0u, ia, off);
        float ho = __shfl_up_sync(~0u, ih, off);
        if (lane >= off) {
            ih = fmaf(ia, ho, ih);
            ia = ia * ao;
        }
    }
    float eh = __shfl_up_sync(~0u, ih, 1);
    if (lane == 0) eh = 0.f;
    g_Hp[bc0 * D_ + d]       = eh;
    g_Hp[(bc0 + 1) * D_ + d] = fmaf(a0, eh, h0);
}

// ---------------- K4: replay + residual + LayerNorm (2 timesteps / round) ----------------
__global__ void __launch_bounds__(512) k_scan3(const float* __restrict__ x,
        const float* __restrict__ gamma, const float* __restrict__ beta,
        float* __restrict__ out) {
    __shared__ float2 red[16];
    __shared__ float2 s_mu, s_rs;
    int bc = blockIdx.x;
    int tid = threadIdx.x;
    int lane = tid & 31, wrp = tid >> 5;
    int d2 = tid * 2;
    float h0 = g_Hp[bc * D_ + d2];
    float h1 = g_Hp[bc * D_ + d2 + 1];
    float2 ga = *(const float2*)(gamma + d2);
    float2 be = *(const float2*)(beta + d2);
    size_t base = (size_t)bc * CL * D_ + d2;
#pragma unroll 1
    for (int t = 0; t < CL; t += 2) {
        size_t i0 = base + (size_t)t * D_;
        size_t i1 = i0 + D_;
        float2 c0 = __half22float2(*(const __half2*)(g_ch + i0));
        float2 v0 = __half22float2(*(const __half2*)(g_vh + i0));
        float2 c1 = __half22float2(*(const __half2*)(g_ch + i1));
        float2 v1 = __half22float2(*(const __half2*)(g_vh + i1));
        float2 xa = *(const float2*)(x + i0);
        float2 xb = *(const float2*)(x + i1);
        h0 = fmaf(c0.x, h0, v0.x); h1 = fmaf(c0.y, h1, v0.y);
        float ya0 = xa.x + h0, ya1 = xa.y + h1;
        h0 = fmaf(c1.x, h0, v1.x); h1 = fmaf(c1.y, h1, v1.y);
        float yb0 = xb.x + h0, yb1 = xb.y + h1;

        float sx = ya0 + ya1, sy = yb0 + yb1;
#pragma unroll
        for (int o = 16; o; o >>= 1) {
            sx += __shfl_xor_sync(~0u, sx, o);
            sy += __shfl_xor_sync(~0u, sy, o);
        }
        if (lane == 0) red[wrp] = make_float2(sx, sy);
        __syncthreads();
        if (wrp == 0) {
            float2 v = (lane < 16) ? red[lane] : make_float2(0.f, 0.f);
#pragma unroll
            for (int o = 8; o; o >>= 1) {
                v.x += __shfl_xor_sync(~0u, v.x, o);
                v.y += __shfl_xor_sync(~0u, v.y, o);
            }
            if (lane == 0) s_mu = make_float2(v.x * (1.f / 1024.f), v.y * (1.f / 1024.f));
        }
        __syncthreads();
        float mua = s_mu.x, mub = s_mu.y;
        float da0 = ya0 - mua, da1 = ya1 - mua;
        float db0 = yb0 - mub, db1 = yb1 - mub;
        float qx = da0 * da0 + da1 * da1, qy = db0 * db0 + db1 * db1;
#pragma unroll
        for (int o = 16; o; o >>= 1) {
            qx += __shfl_xor_sync(~0u, qx, o);
            qy += __shfl_xor_sync(~0u, qy, o);
        }
        if (lane == 0) red[wrp] = make_float2(qx, qy);
        __syncthreads();
        if (wrp == 0) {
            float2 v = (lane < 16) ? red[lane] : make_float2(0.f, 0.f);
#pragma unroll
            for (int o = 8; o; o >>= 1) {
                v.x += __shfl_xor_sync(~0u, v.x, o);
                v.y += __shfl_xor_sync(~0u, v.y, o);
            }
            if (lane == 0) s_rs = make_float2(rsqrtf(v.x * (1.f / 1024.f) + LN_EPS),
                                              rsqrtf(v.y * (1.f / 1024.f) + LN_EPS));
        }
        __syncthreads();
        float rsa = s_rs.x, rsb = s_rs.y;
        float2 oa, ob;
        oa.x = da0 * rsa * ga.x + be.x;  oa.y = da1 * rsa * ga.y + be.y;
        ob.x = db0 * rsb * ga.x + be.x;  ob.y = db1 * rsb * ga.y + be.y;
        *(float2*)(out + i0) = oa;
        *(float2*)(out + i1) = ob;
    }
}

extern "C" void kernel_launch(void* const* d_in, const int* in_sizes, int n_in,
                              void* d_out, int out_size) {
    const float* x     = (const float*)d_in[0];
    const float* W     = (const float*)d_in[1];
    const float* b     = (const float*)d_in[2];
    const float* gamma = (const float*)d_in[3];
    const float* beta  = (const float*)d_in[4];
    float* out = (float*)d_out;

    cudaFuncSetAttribute(k_gemm, cudaFuncAttributeMaxDynamicSharedMemorySize, SMEM_DYN);

    k_cvt_x<<<(BT * 128) / 256, 256>>>((const float4*)x);
    k_wt<<<dim3(N2 / 32, D_ / 32), dim3(32, 8)>>>(W);
    k_gemm<<<dim3(D_ / 64, BT / 128), 256, SMEM_DYN>>>(b);
    k_scan2<<<(B_ * D_ * 32) / 256, 256>>>();
    k_scan3<<<B_ * NCH, 512>>>(x, gamma, beta, out);
}

// round 8
// speedup vs baseline: 1.7126x; 1.0261x over previous
#include <cuda_runtime.h>
#include <cuda_fp16.h>
#include <cstdint>

#define DEV __device__ __forceinline__

static constexpr int B_  = 8;
static constexpr int T_  = 4096;
static constexpr int D_  = 1024;
static constexpr int BT  = B_ * T_;        // 32768
static constexpr int N2  = 2 * D_;         // 2048
static constexpr int NCH = 64;
static constexpr int CL  = T_ / NCH;       // 64
static constexpr float LN_EPS = 1e-6f;

// pre-tiled operands: tile (blk, kt) = contiguous 4096 halves (8KB)
// element (row r 0..127, k-half kk 0..31): granule j=kk>>3, b=kk&7
// offset = ((blk*32+kt)*128 + r)*32 + ((j + (r>>1))&3)*8 + b   [halves]
__device__ __align__(16) __half g_xh[(size_t)BT * D_];   // x tiled fp16
__device__ __align__(16) __half g_wt[(size_t)N2 * D_];   // W^T tiled fp16
__device__ __align__(16) __half g_ch[(size_t)BT * D_];   // gate coeff (fp16, flat)
__device__ __align__(16) __half g_vh[(size_t)BT * D_];   // gate value (fp16, flat)
__device__ float g_A [B_ * NCH * D_];
__device__ float g_Hl[B_ * NCH * D_];
__device__ float g_Hp[B_ * NCH * D_];

DEV uint32_t smem_u32(const void* p) {
    uint32_t a;
    asm("{ .reg .u64 t; cvta.to.shared.u64 t, %1; cvt.u32.u64 %0, t; }" : "=r"(a) : "l"(p));
    return a;
}

#define MBAR_INIT(a, c) \
    asm volatile("mbarrier.init.shared.b64 [%0], %1;" :: "r"((uint32_t)(a)), "r"((uint32_t)(c)) : "memory")
#define MBAR_EXPECT_TX(a, tx) \
    asm volatile("mbarrier.arrive.expect_tx.shared.b64 _, [%0], %1;" :: "r"((uint32_t)(a)), "r"((uint32_t)(tx)) : "memory")
#define MBAR_WAIT(a, par) do {                                                             \
    uint32_t _m = (uint32_t)(a); uint32_t _p = (uint32_t)(par); uint32_t _d;               \
    asm volatile("{\n\t.reg .pred p;\n\t"                                                  \
        "mbarrier.try_wait.parity.acquire.cta.shared::cta.b64 p, [%1], %2;\n\t"            \
        "selp.b32 %0, 1, 0, p;\n\t}" : "=r"(_d) : "r"(_m), "r"(_p) : "memory");            \
    if (!_d) {                                                                             \
        asm volatile("{\n\t.reg .pred P1;\n\t"                                             \
            "WL_%=:\n\t"                                                                   \
            "mbarrier.try_wait.parity.acquire.cta.shared::cta.b64 P1, [%0], %1, 0x989680;\n\t" \
            "@P1 bra.uni WD_%=;\n\t bra.uni WL_%=;\n\t WD_%=:\n\t}"                        \
            :: "r"(_m), "r"(_p) : "memory");                                               \
    } } while (0)
#define BULK_G2S(dst, src, bytes, mbar) \
    asm volatile("cp.async.bulk.shared::cta.global.mbarrier::complete_tx::bytes [%0], [%1], %2, [%3];" \
        :: "r"((uint32_t)(dst)), "l"(src), "r"((uint32_t)(bytes)), "r"((uint32_t)(mbar)) : "memory")
#define FENCE_ASYNC() asm volatile("fence.proxy.async.shared::cta;" ::: "memory")

#define LDSM4(r0, r1, r2, r3, addr) \
    asm volatile("ldmatrix.sync.aligned.m8n8.x4.shared.b16 {%0,%1,%2,%3}, [%4];" \
        : "=r"(r0), "=r"(r1), "=r"(r2), "=r"(r3) : "r"(addr))

#define MMA(d, a0, a1, a2, a3, b0, b1) \
    asm volatile("mma.sync.aligned.m16n8k16.row.col.f32.f16.f16.f32 " \
        "{%0,%1,%2,%3}, {%4,%5,%6,%7}, {%8,%9}, {%0,%1,%2,%3};" \
        : "+f"((d)[0]), "+f"((d)[1]), "+f"((d)[2]), "+f"((d)[3]) \
        : "r"(a0), "r"(a1), "r"(a2), "r"(a3), "r"(b0), "r"(b1))

// ---------------- K0a: x fp32 -> fp16, tiled+swizzled ----------------
__global__ void __launch_bounds__(256) k_cvt_x(const float4* __restrict__ x4) {
    int g = blockIdx.x * blockDim.x + threadIdx.x;       // 16-byte granule id
    if (g >= BT * 128) return;
    int m = g >> 7, gk = g & 127;
    int kt = gk >> 2, j = gk & 3;
    float4 v0 = x4[(size_t)g * 2];
    float4 v1 = x4[(size_t)g * 2 + 1];
    __half2 h0 = __floats2half2_rn(v0.x, v0.y), h1 = __floats2half2_rn(v0.z, v0.w);
    __half2 h2 = __floats2half2_rn(v1.x, v1.y), h3 = __floats2half2_rn(v1.z, v1.w);
    uint4 u;
    u.x = *(uint32_t*)&h0; u.y = *(uint32_t*)&h1;
    u.z = *(uint32_t*)&h2; u.w = *(uint32_t*)&h3;
    int r = m & 127;
    size_t off = ((size_t)((m >> 7) * 32 + kt) * 128 + r) * 32
               + (size_t)(((j + (r >> 1)) & 3) * 8);
    *(uint4*)(g_xh + off) = u;
}

// ---------------- K0b: W[D,2D] -> W^T fp16, tiled+swizzled ----------------
__global__ void k_wt(const float* __restrict__ W) {
    __shared__ float tile[32][33];
    int e0 = blockIdx.x * 32, d0 = blockIdx.y * 32;
    int tx = threadIdx.x, ty = threadIdx.y;
#pragma unroll
    for (int jj = 0; jj < 4; ++jj)
        tile[ty + 8 * jj][tx] = W[(size_t)(d0 + ty + 8 * jj) * N2 + e0 + tx];
    __syncthreads();
#pragma unroll
    for (int jj = 0; jj < 4; ++jj) {
        int e = e0 + ty + 8 * jj;
        int d = d0 + tx;
        int jblk  = (e < 1024) ? (e >> 6) : ((e - 1024) >> 6);
        int rowIn = (e < 1024) ? (e & 63) : (64 + (e & 63));
        int kt = d >> 5, kk = d & 31;
        int jg = kk >> 3, bb = kk & 7;
        size_t off = ((size_t)(jblk * 32 + kt) * 128 + rowIn) * 32
                   + (size_t)(((jg + (rowIn >> 1)) & 3) * 8 + bb);
        g_wt[off] = __float2half_rn(tile[tx][ty + 8 * jj]);
    }
}

// ---------------- K1: HMMA GEMM (6-slot bulk pipeline) + gates + local scan ----------------
static constexpr int SLOT_B   = 16384;               // A 8KB + B 8KB per kt
static constexpr int NBUF     = 6;
static constexpr int MBAR_OFF = NBUF * SLOT_B;       // 98304
static constexpr int SMEM_EPI = 2 * 128 * 72 * 4 + 2048;
static constexpr int SMEM_DYN = (MBAR_OFF + 64 > SMEM_EPI) ? (MBAR_OFF + 64) : SMEM_EPI;

DEV void gate(float ht, float kk, float& c, float& v) {
    float ek = __expf(kk);
    c = 1.f / (1.f + ek);                   // sigmoid(-k)
    float z = 1.f - c;                      // sigmoid(k)
    float g = (ht >= 0.f) ? (ht + 0.5f) : (1.f / (1.f + __expf(-ht)));
    v = z * g;
}

__global__ void __launch_bounds__(256) k_gemm(const float* __restrict__ bias) {
    extern __shared__ char smem[];
    uint32_t sb = smem_u32(smem);
    int tid = threadIdx.x;
    int wid = tid >> 5, lane = tid & 31;
    int wm = wid & 3, wn = wid >> 2;        // 4m x 2n warp grid, warp tile m32 x n64
    int mt = blockIdx.y;                    // m-tile (128 rows)
    int jb = blockIdx.x;                    // j block (64 pairs)
    int m0 = mt * 128, j0 = jb * 64;

    const __half* Asrc = g_xh + (size_t)mt * 32 * 4096;
    const __half* Bsrc = g_wt + (size_t)jb * 32 * 4096;

    if (tid == 0) {
#pragma unroll
        for (int s = 0; s < NBUF; ++s) MBAR_INIT(sb + MBAR_OFF + 8 * s, 1);
        FENCE_ASYNC();
    }
    __syncthreads();
    if (tid == 0) {
#pragma unroll
        for (int kt = 0; kt < 4; ++kt) {          // prefetch distance 4
            uint32_t mb = sb + MBAR_OFF + 8 * (kt % NBUF);
            MBAR_EXPECT_TX(mb, 16384);
            BULK_G2S(sb + (kt % NBUF) * SLOT_B,        Asrc + (size_t)kt * 4096, 8192, mb);
            BULK_G2S(sb + (kt % NBUF) * SLOT_B + 8192, Bsrc + (size_t)kt * 4096, 8192, mb);
        }
    }

    float acc[2][8][4] = {};

    // ldmatrix lane addressing (swizzled tiled layout)
    int la15 = lane & 15, lhi = lane >> 4;
    int rA = wm * 32 + la15;
    uint32_t aRow = (uint32_t)rA * 64;
    uint32_t aCol0 = (uint32_t)(((lhi + (rA >> 1)) & 3) << 4);          // s=0
    int rB = wn * 64 + ((lane & 7) | (lhi << 3));
    uint32_t bRow = (uint32_t)rB * 64;
    uint32_t bCol0 = (uint32_t)(((((lane >> 3) & 1) + (rB >> 1)) & 3) << 4);

    // paired k-tiles, 6 slots, prefetch distance 4: at the top of pair
    // (kt,kt+1) issue copies for kt+4/kt+5. Slot (kt+4)%6 was last read at
    // kt-2 (previous pair) — ordered by this pair's __syncthreads.
#pragma unroll 1
    for (int kt = 0; kt < 32; kt += 2) {
        __syncthreads();
        if (tid == 0 && kt + 4 < 32) {
#pragma unroll
            for (int q = 4; q < 6; ++q) {
                int sl = (kt + q) % NBUF;
                uint32_t mb = sb + MBAR_OFF + 8 * sl;
                MBAR_EXPECT_TX(mb, 16384);
                BULK_G2S(sb + sl * SLOT_B,        Asrc + (size_t)(kt + q) * 4096, 8192, mb);
                BULK_G2S(sb + sl * SLOT_B + 8192, Bsrc + (size_t)(kt + q) * 4096, 8192, mb);
            }
        }
#pragma unroll
        for (int q = 0; q < 2; ++q) {
            int ktq = kt + q;
            MBAR_WAIT(sb + MBAR_OFF + 8 * (ktq % NBUF), (ktq / NBUF) & 1);
            uint32_t Ab = sb + (uint32_t)(ktq % NBUF) * SLOT_B;
            uint32_t Bb = Ab + 8192;
#pragma unroll
            for (int s = 0; s < 2; ++s) {
                uint32_t aCol = aCol0 ^ (s << 5);
                uint32_t bCol = bCol0 ^ (s << 5);
                uint32_t a[2][4];
#pragma unroll
                for (int mi = 0; mi < 2; ++mi)
                    LDSM4(a[mi][0], a[mi][1], a[mi][2], a[mi][3],
                          Ab + aRow + (uint32_t)mi * 1024 + aCol);
#pragma unroll
                for (int ni = 0; ni < 4; ++ni) {
                    uint32_t b0, b1, b2, b3;
                    LDSM4(b0, b1, b2, b3, Bb + bRow + (uint32_t)ni * 1024 + bCol);
#pragma unroll
                    for (int mi = 0; mi < 2; ++mi) {
                        MMA(acc[mi][2 * ni],     a[mi][0], a[mi][1], a[mi][2], a[mi][3], b0, b1);
                        MMA(acc[mi][2 * ni + 1], a[mi][0], a[mi][1], a[mi][2], a[mi][3], b2, b3);
                    }
                }
            }
        }
    }
    __syncthreads();   // drained; reuse smem for epilogue

    // ---- stage raw projections (+bias); wn=0 -> h~, wn=1 -> k ----
    float* hst = (float*)smem;           // 128 x 72
    float* kst = hst + 128 * 72;
    float* sA  = kst + 128 * 72;         // 256 seg aggregates
    float* sH  = sA + 256;
    {
        const float* bptr = bias + (wn ? (1024 + j0) : j0);
        float* dst = wn ? kst : hst;
        int rb = wm * 32 + (lane >> 2);
        int cb = (lane & 3) * 2;
#pragma unroll
        for (int mi = 0; mi < 2; ++mi) {
#pragma unroll
            for (int nj = 0; nj < 8; ++nj) {
                int r = rb + mi * 16;
                int c = nj * 8 + cb;
                float b0v = bptr[c], b1v = bptr[c + 1];
                dst[r * 72 + c]           = acc[mi][nj][0] + b0v;
                dst[r * 72 + c + 1]       = acc[mi][nj][1] + b1v;
                dst[(r + 8) * 72 + c]     = acc[mi][nj][2] + b0v;
                dst[(r + 8) * 72 + c + 1] = acc[mi][nj][3] + b1v;
            }
        }
    }
    __syncthreads();

    // ---- elementwise gate in place: hst <- c, kst <- v ----
#pragma unroll 4
    for (int i = 0; i < 32; ++i) {
        int e = i * 256 + tid;
        int r = e >> 6, c = e & 63;
        float cc, vv;
        gate(hst[r * 72 + c], kst[r * 72 + c], cc, vv);
        hst[r * 72 + c] = cc;
        kst[r * 72 + c] = vv;
    }
    __syncthreads();

    // fused local scan, phase 1: each thread scans 32 rows of one d-column
    {
        int seg  = tid >> 6;            // (chunk<<1)|half
        int dcol = tid & 63;
        int rs = seg * 32;
        float a = 1.f, h = 0.f;
#pragma unroll 8
        for (int t = 0; t < 32; ++t) {
            float c = hst[(rs + t) * 72 + dcol];
            float v = kst[(rs + t) * 72 + dcol];
            h = fmaf(c, h, v);
            a *= c;
        }
        sA[tid] = a; sH[tid] = h;
    }

    // coalesced fp16 stores of c/v (flat layout)
#pragma unroll
    for (int i = 0; i < 8; ++i) {
        int e = i * 256 + tid;
        int r = e >> 4, q = e & 15;
        size_t go = (size_t)(m0 + r) * D_ + j0 + q * 4;
        float4 cf = *(float4*)(hst + r * 72 + q * 4);
        float4 vf = *(float4*)(kst + r * 72 + q * 4);
        __half2 ca = __floats2half2_rn(cf.x, cf.y), cbh = __floats2half2_rn(cf.z, cf.w);
        __half2 va = __floats2half2_rn(vf.x, vf.y), vb = __floats2half2_rn(vf.z, vf.w);
        uint2 cu, vu;
        cu.x = *(uint32_t*)&ca; cu.y = *(uint32_t*)&cbh;
        vu.x = *(uint32_t*)&va; vu.y = *(uint32_t*)&vb;
        *(uint2*)(g_ch + go) = cu;
        *(uint2*)(g_vh + go) = vu;
    }
    __syncthreads();

    // local scan, phase 2: combine halves -> chunk aggregates
    if (tid < 128) {
        int chunk = tid >> 6, dcol = tid & 63;
        float aLo = sA[chunk * 128 + dcol],      hLo = sH[chunk * 128 + dcol];
        float aHi = sA[chunk * 128 + 64 + dcol], hHi = sH[chunk * 128 + 64 + dcol];
        int bc = (m0 >> 6) + chunk;
        g_A [bc * D_ + j0 + dcol] = aLo * aHi;
        g_Hl[bc * D_ + j0 + dcol] = fmaf(aHi, hLo, hHi);
    }
}

// ---------------- K3: cross-chunk prefix, warp Kogge-Stone ----------------
__global__ void __launch_bounds__(256) k_scan2() {
    int t = blockIdx.x * blockDim.x + threadIdx.x;
    int w = t >> 5;
    int lane = t & 31;
    int b = w >> 10, d = w & (D_ - 1);
    int bc0 = b * NCH + lane * 2;
    float a0 = g_A [bc0 * D_ + d];
    float h0 = g_Hl[bc0 * D_ + d];
    float a1 = g_A [(bc0 + 1) * D_ + d];
    float h1 = g_Hl[(bc0 + 1) * D_ + d];
    float ia = a0 * a1;
    float ih = fmaf(a1, h0, h1);
#pragma unroll
    for (int off = 1; off < 32; off <<= 1) {
        float ao = __shfl_up_sync(~0u, ia, off);
        float ho = __shfl_up_sync(~0u, ih, off);
        if (lane >= off) {
            ih = fmaf(ia, ho, ih);
            ia = ia * ao;
        }
    }
    float eh = __shfl_up_sync(~0u, ih, 1);
    if (lane == 0) eh = 0.f;
    g_Hp[bc0 * D_ + d]       = eh;
    g_Hp[(bc0 + 1) * D_ + d] = fmaf(a0, eh, h0);
}

// ---------------- K4: replay + residual + LayerNorm (x read from fp16 tiles) ----------------
__global__ void __launch_bounds__(512) k_scan3(
        const float* __restrict__ gamma, const float* __restrict__ beta,
        float* __restrict__ out) {
    __shared__ float2 red[16];
    __shared__ float2 s_mu, s_rs;
    int bc = blockIdx.x;
    int tid = threadIdx.x;
    int lane = tid & 31, wrp = tid >> 5;
    int d2 = tid * 2;
    float h0 = g_Hp[bc * D_ + d2];
    float h1 = g_Hp[bc * D_ + d2 + 1];
    float2 ga = *(const float2*)(gamma + d2);
    float2 be = *(const float2*)(beta + d2);
    size_t base = (size_t)bc * CL * D_ + d2;
    // tiled-x addressing: global row m = bc*64 + t -> tile mt=bc>>1, r=(bc&1)*64+t
    int r0  = (bc & 1) * 64;
    int ktd = d2 >> 5, jg = (d2 >> 3) & 3, bb = d2 & 7;
    const __half* xtile = g_xh + (size_t)((bc >> 1) * 32 + ktd) * 4096;
#pragma unroll 1
    for (int t = 0; t < CL; t += 2) {
        size_t i0 = base + (size_t)t * D_;
        size_t i1 = i0 + D_;
        float2 c0 = __half22float2(*(const __half2*)(g_ch + i0));
        float2 v0 = __half22float2(*(const __half2*)(g_vh + i0));
        float2 c1 = __half22float2(*(const __half2*)(g_ch + i1));
        float2 v1 = __half22float2(*(const __half2*)(g_vh + i1));
        int r = r0 + t;                                   // even
        const __half* pa = xtile + r * 32 + ((jg + (r >> 1)) & 3) * 8 + bb;
        float2 xa = __half22float2(*(const __half2*)pa);
        float2 xb = __half22float2(*(const __half2*)(pa + 32));
        h0 = fmaf(c0.x, h0, v0.x); h1 = fmaf(c0.y, h1, v0.y);
        float ya0 = xa.x + h0, ya1 = xa.y + h1;
        h0 = fmaf(c1.x, h0, v1.x); h1 = fmaf(c1.y, h1, v1.y);
        float yb0 = xb.x + h0, yb1 = xb.y + h1;

        float sx = ya0 + ya1, sy = yb0 + yb1;
#pragma unroll
        for (int o = 16; o; o >>= 1) {
            sx += __shfl_xor_sync(~0u, sx, o);
            sy += __shfl_xor_sync(~0u, sy, o);
        }
        if (lane == 0) red[wrp] = make_float2(sx, sy);
        __syncthreads();
        if (wrp == 0) {
            float2 v = (lane < 16) ? red[lane] : make_float2(0.f, 0.f);
#pragma unroll
            for (int o = 8; o; o >>= 1) {
                v.x += __shfl_xor_sync(~0u, v.x, o);
                v.y += __shfl_xor_sync(~0u, v.y, o);
            }
            if (lane == 0) s_mu = make_float2(v.x * (1.f / 1024.f), v.y * (1.f / 1024.f));
        }
        __syncthreads();
        float mua = s_mu.x, mub = s_mu.y;
        float da0 = ya0 - mua, da1 = ya1 - mua;
        float db0 = yb0 - mub, db1 = yb1 - mub;
        float qx = da0 * da0 + da1 * da1, qy = db0 * db0 + db1 * db1;
#pragma unroll
        for (int o = 16; o; o >>= 1) {
            qx += __shfl_xor_sync(~0u, qx, o);
            qy += __shfl_xor_sync(~0u, qy, o);
        }
        if (lane == 0) red[wrp] = make_float2(qx, qy);
        __syncthreads();
        if (wrp == 0) {
            float2 v = (lane < 16) ? red[lane] : make_float2(0.f, 0.f);
#pragma unroll
            for (int o = 8; o; o >>= 1) {
                v.x += __shfl_xor_sync(~0u, v.x, o);
                v.y += __shfl_xor_sync(~0u, v.y, o);
            }
            if (lane == 0) s_rs = make_float2(rsqrtf(v.x * (1.f / 1024.f) + LN_EPS),
                                              rsqrtf(v.y * (1.f / 1024.f) + LN_EPS));
        }
        __syncthreads();
        float rsa = s_rs.x, rsb = s_rs.y;
        float2 oa, ob;
        oa.x = da0 * rsa * ga.x + be.x;  oa.y = da1 * rsa * ga.y + be.y;
        ob.x = db0 * rsb * ga.x + be.x;  ob.y = db1 * rsb * ga.y + be.y;
        *(float2*)(out + i0) = oa;
        *(float2*)(out + i1) = ob;
    }
}

extern "C" void kernel_launch(void* const* d_in, const int* in_sizes, int n_in,
                              void* d_out, int out_size) {
    const float* x     = (const float*)d_in[0];
    const float* W     = (const float*)d_in[1];
    const float* b     = (const float*)d_in[2];
    const float* gamma = (const float*)d_in[3];
    const float* beta  = (const float*)d_in[4];
    float* out = (float*)d_out;

    cudaFuncSetAttribute(k_gemm, cudaFuncAttributeMaxDynamicSharedMemorySize, SMEM_DYN);

    k_cvt_x<<<(BT * 128) / 256, 256>>>((const float4*)x);
    k_wt<<<dim3(N2 / 32, D_ / 32), dim3(32, 8)>>>(W);
    k_gemm<<<dim3(D_ / 64, BT / 128), 256, SMEM_DYN>>>(b);
    k_scan2<<<(B_ * D_ * 32) / 256, 256>>>();
    k_scan3<<<B_ * NCH, 512>>>(gamma, beta, out);
}